// round 12
// baseline (speedup 1.0000x reference)
#include <cuda_runtime.h>
#include <cuda_bf16.h>
#include <cstdint>

// ============================================================================
// Arch gating: tcgen05/TMEM are sm_103a ("arch-specific") features. The
// harness also compiles a plain compute_103 stage, which must not see any
// tcgen05 PTX. HAS_TC selects the real tensor-core path only on the
// arch-specific device pass; all other passes get a correct FFMA fallback.
// ============================================================================
#if defined(__CUDA_ARCH__) && \
    (defined(__CUDA_ARCH_FEAT_SM103_ALL) || defined(__CUDA_ARCH_FEAT_SM100_ALL) || \
     defined(__CUDA_ARCH_SPECIFIC__) || defined(__CUDA_ARCH_FAMILY_SPECIFIC__))
#define HAS_TC 1
#else
#define HAS_TC 0
#endif

// ============================================================================
// Problem constants: B=8192 (derived at launch), U=16, I=H=128, 3H=384 gates
// ============================================================================
#define U_DIM 16
#define I_DIM 128
#define H_DIM 128
#define G3    384
#define W_ELEMS (U_DIM * G3 * I_DIM)   // 786432 per weight matrix

// Pre-split weights (fp32 -> bf16 hi + bf16 lo), filled by prep kernel.
__device__ __nv_bfloat16 g_wih_hi[W_ELEMS];
__device__ __nv_bfloat16 g_wih_lo[W_ELEMS];
__device__ __nv_bfloat16 g_whh_hi[W_ELEMS];
__device__ __nv_bfloat16 g_whh_lo[W_ELEMS];

// ============================================================================
// PTX helpers
// ============================================================================
__device__ __forceinline__ uint32_t elect_one_pred() {
    uint32_t pred;
    asm volatile(
        "{\n\t"
        ".reg .pred p;\n\t"
        "elect.sync _|p, 0xFFFFFFFF;\n\t"
        "selp.b32 %0, 1, 0, p;\n\t"
        "}"
        : "=r"(pred));
    return pred;
}

__device__ __forceinline__ uint32_t smem_to_u32(const void* smem_ptr) {
    uint32_t addr;
    asm("{ .reg .u64 tmp; cvta.to.shared.u64 tmp, %1; cvt.u32.u64 %0, tmp; }"
        : "=r"(addr) : "l"(smem_ptr));
    return addr;
}

__device__ __forceinline__ uint32_t cluster_rank() {
    uint32_t r;
    asm("mov.u32 %0, %%cluster_ctarank;" : "=r"(r));
    return r;
}

#define CLUSTER_SYNC() do { \
    asm volatile("barrier.cluster.arrive.aligned;" ::: "memory"); \
    asm volatile("barrier.cluster.wait.aligned;" ::: "memory"); \
} while (0)

// SW64 swizzle: atom = 8 rows x 64 bytes
#define SMEM_SWIZZLE_64B(byte_offset) \
    ((byte_offset) ^ (((byte_offset) >> 3) & 0x30))

// SW64 smem descriptor: layout=4, version=1 (Blackwell), SBO=32 (512B per
// 8-row group), LBO=1 (16B inner stride). Rows are 64B wide.
static constexpr uint64_t SMEM_DESC_BASE_SW64 =
    (uint64_t(4)  << 61)
    | (uint64_t(1) << 46)
    | (uint64_t(32) << 32)
    | (uint64_t(1) << 16);

#define MAKE_SMEM_DESC64(base_addr) \
    (SMEM_DESC_BASE_SW64 | ((uint64_t)((base_addr) >> 4) & 0x3FFF))

#define TCGEN05_ALLOC_CG2(smem_result_addr, nCols) \
    asm volatile( \
        "tcgen05.alloc.cta_group::2.sync.aligned.shared::cta.b32 [%0], %1;" \
        :: "r"((uint32_t)(smem_result_addr)), "r"((uint32_t)(nCols)) \
        : "memory")

#define TCGEN05_DEALLOC_CG2(tmem_addr, nCols) \
    asm volatile( \
        "tcgen05.dealloc.cta_group::2.sync.aligned.b32 %0, %1;" \
        :: "r"(tmem_addr), "r"((uint32_t)(nCols)))

#define TCGEN05_RELINQUISH_CG2() \
    asm volatile("tcgen05.relinquish_alloc_permit.cta_group::2.sync.aligned;")

#define TCGEN05_COMMIT_MCAST_CG2(mbar_smem_addr, cta_mask) \
    asm volatile( \
        "tcgen05.commit.cta_group::2.mbarrier::arrive::one.shared::cluster.multicast::cluster.b64 [%0], %1;" \
        :: "r"((uint32_t)(mbar_smem_addr)), "h"((uint16_t)(cta_mask)) \
        : "memory")

#define TCGEN05_FENCE_AFTER() \
    asm volatile("tcgen05.fence::after_thread_sync;" ::: "memory")

#define TCGEN05_FENCE_BEFORE() \
    asm volatile("tcgen05.fence::before_thread_sync;" ::: "memory")

#define TCGEN05_WAIT_LD() \
    asm volatile("tcgen05.wait::ld.sync.aligned;" ::: "memory")

#define FENCE_PROXY_ASYNC_SHARED_CTA() \
    asm volatile("fence.proxy.async.shared::cta;" ::: "memory")

#define MBARRIER_INIT(mbar_smem_addr, count) \
    asm volatile( \
        "mbarrier.init.shared.b64 [%0], %1;" \
        :: "r"((uint32_t)(mbar_smem_addr)), "r"((uint32_t)(count)) \
        : "memory")

// Arrive (release.cluster) on the mbarrier at the same SMEM offset in CTA
// `target_rank` of this cluster.
#define MBARRIER_ARRIVE_CLUSTER(local_mbar_addr, target_rank) \
    asm volatile( \
        "{\n\t" \
        ".reg .b32 remAddr32;\n\t" \
        "mapa.shared::cluster.u32 remAddr32, %0, %1;\n\t" \
        "mbarrier.arrive.release.cluster.shared::cluster.b64 _, [remAddr32];\n\t" \
        "}" \
        :: "r"((uint32_t)(local_mbar_addr)), "r"((uint32_t)(target_rank)) \
        : "memory")

#define MBARRIER_WAIT_PARITY_SC(mbar_smem_addr, phase_parity, SCOPE) do { \
    uint32_t _mbar = (uint32_t)(mbar_smem_addr); \
    uint32_t _parity = (uint32_t)(phase_parity); \
    uint32_t _done; \
    asm volatile( \
        "{\n\t" \
        ".reg .pred p;\n\t" \
        "mbarrier.try_wait.parity.acquire." SCOPE ".shared::cta.b64 p, [%1], %2;\n\t" \
        "selp.b32 %0, 1, 0, p;\n\t" \
        "}" \
        : "=r"(_done) : "r"(_mbar), "r"(_parity) : "memory"); \
    if (!_done) { \
        asm volatile( \
            "{\n\t" \
            ".reg .pred P1;\n\t" \
            "WAIT_LOOP_%=:\n\t" \
            "mbarrier.try_wait.parity.acquire." SCOPE ".shared::cta.b64 P1, [%0], %1, 0x989680;\n\t" \
            "@P1 bra.uni WAIT_DONE_%=;\n\t" \
            "bra.uni WAIT_LOOP_%=;\n\t" \
            "WAIT_DONE_%=:\n\t" \
            "}" \
            :: "r"(_mbar), "r"(_parity) : "memory"); \
    } \
} while(0)

#define MBARRIER_WAIT_PARITY(mbar, par)     MBARRIER_WAIT_PARITY_SC(mbar, par, "cta")
#define MBARRIER_WAIT_PARITY_CLU(mbar, par) MBARRIER_WAIT_PARITY_SC(mbar, par, "cluster")

#define TCGEN05_LD_32X32B_X16(r, tmem_addr) \
    asm volatile( \
        "tcgen05.ld.sync.aligned.32x32b.x16.b32 " \
        "{%0, %1, %2, %3, %4, %5, %6, %7, " \
        " %8, %9, %10, %11, %12, %13, %14, %15}, [%16];" \
        : "=r"((r)[0]),  "=r"((r)[1]),  "=r"((r)[2]),  "=r"((r)[3]), \
          "=r"((r)[4]),  "=r"((r)[5]),  "=r"((r)[6]),  "=r"((r)[7]), \
          "=r"((r)[8]),  "=r"((r)[9]),  "=r"((r)[10]), "=r"((r)[11]), \
          "=r"((r)[12]), "=r"((r)[13]), "=r"((r)[14]), "=r"((r)[15]) \
        : "r"(tmem_addr))

#if HAS_TC
// SS-mode cg2 bf16 MMA (kind::f16), fp32 accumulate in TMEM. M=256 across the
// CTA pair: A rows 128*rank..+128 from each CTA's smem at the same offset;
// B split N/2 (64 rows) per CTA at the same offset.
__device__ __forceinline__ void mma_f16_ss_cg2(uint32_t d_tmem, uint64_t a_desc,
                                               uint64_t b_desc, uint32_t idesc,
                                               uint32_t en) {
    asm volatile(
        "{\n\t"
        ".reg .pred p;\n\t"
        "setp.ne.u32 p, %5, 0;\n\t"
        "tcgen05.mma.cta_group::2.kind::f16 [%0], %1, %2, %3, "
        "{%4, %4, %4, %4, %4, %4, %4, %4}, p;\n\t"
        "}"
        :: "r"(d_tmem), "l"(a_desc), "l"(b_desc), "r"(idesc), "r"(0u), "r"(en)
        : "memory");
}

// 16-byte async copy, L2-only (.cg): streamed weights have no L1 reuse.
__device__ __forceinline__ void cp_async_16(uint32_t saddr, const void* gptr) {
    asm volatile(
        "{\n\t"
        ".reg .u64 g;\n\t"
        "cvta.to.global.u64 g, %1;\n\t"
        "cp.async.cg.shared.global [%0], [g], 16;\n\t"
        "}"
        :: "r"(saddr), "l"(gptr) : "memory");
}
#endif

// ============================================================================
// Shared memory layout. K-chunk = 32 (64B rows, SW64). FOUR pipeline stages.
// Per stage: A_HI 8KB | A_LO 8KB | B_HI 12KB | B_LO 12KB = 40KB.
// (B is split N/2 per CTA under cg2: 3 N-tiles x 64 rows x 64B.)
// ============================================================================
static constexpr int SMEM_TMEMPTR   = 0;
static constexpr int SMEM_DONE      = 8;    // 4 x 8B: per-stage "mma done"
static constexpr int SMEM_READY     = 40;   // 4 x 8B: per-stage "tiles ready" (leader's used)
static constexpr int SMEM_BIAS      = 128;  // 512 floats
static constexpr int SMEM_STAGE_SZ  = 40960;
static constexpr int SMEM_STAGES    = 4096;
static constexpr int OFF_A_HI       = 0;      // 128 x 64B = 8 KB
static constexpr int OFF_A_LO       = 8192;   // 8 KB
static constexpr int OFF_B_HI       = 16384;  // 192 x 64B = 12 KB
static constexpr int OFF_B_LO       = 28672;  // 12 KB
static constexpr int SMEM_TOTAL     = SMEM_STAGES + 4 * SMEM_STAGE_SZ; // 167936

// idesc kind::f16 cg2: dtype=F32, atype=btype=BF16, N=128, M=256
static constexpr uint32_t IDESC_CG2 =
    (1u << 4) | (1u << 7) | (1u << 10) | ((128u / 8) << 17) | ((256u / 16) << 24);

// ============================================================================
// Prep kernel: split fp32 weights into bf16 hi/lo pairs
// ============================================================================
__global__ void __launch_bounds__(256) gru_prep(const float* __restrict__ w_ih,
                                                const float* __restrict__ w_hh) {
    int i = blockIdx.x * 256 + threadIdx.x;
    if (i >= W_ELEMS) return;
    float v = w_ih[i];
    __nv_bfloat16 h = __float2bfloat16(v);
    g_wih_hi[i] = h;
    g_wih_lo[i] = __float2bfloat16(v - __bfloat162float(h));
    v = w_hh[i];
    h = __float2bfloat16(v);
    g_whh_hi[i] = h;
    g_whh_lo[i] = __float2bfloat16(v - __bfloat162float(h));
}

// ============================================================================
// Main fused GRU kernel. Cluster of 2 CTAs = (u, 256-row batch tile); each
// CTA owns 128 rows. 256 threads. TMEM D (per CTA, its own 128 rows):
// [0:128)=r_sum [128:256)=z_sum [256:384)=xn [384:512)=hn.
// 8 chunks (2 sides x 4 K32-chunks), 4 smem stages, cg2 MMA issued by rank 0.
// ============================================================================
__global__ void __launch_bounds__(256, 1) __cluster_dims__(2, 1, 1)
gru_main(
    const float* __restrict__ inputs,
    const float* __restrict__ hidden,
    const float* __restrict__ w_ih,
    const float* __restrict__ w_hh,
    const float* __restrict__ b_ih,
    const float* __restrict__ b_hh,
    float* __restrict__ out)
{
    extern __shared__ __align__(1024) char smem[];
    const int tid = threadIdx.x;
    const int u   = blockIdx.y;
    const int b0  = blockIdx.x * 128;        // this CTA's 128 batch rows

#if HAS_TC
    const uint32_t smem_base = smem_to_u32(smem);
    const int wid  = tid >> 5;
    const int lid  = tid & 31;
    const uint32_t rank = cluster_rank();    // == blockIdx.x & 1

    if (wid == 0) {
        TCGEN05_ALLOC_CG2(smem_base + SMEM_TMEMPTR, 512);
        TCGEN05_RELINQUISH_CG2();
    }
    if (tid == 0) {
        #pragma unroll
        for (int s = 0; s < 4; s++) {
            MBARRIER_INIT(smem_base + SMEM_DONE  + s * 8, 1);  // tcgen05 commit
            MBARRIER_INIT(smem_base + SMEM_READY + s * 8, 2);  // 1 arrive per CTA
        }
    }

    float* bias = (float*)(smem + SMEM_BIAS);
    for (int g = tid; g < G3; g += 256) {
        float bi = b_ih[u * G3 + g];
        float bh = b_hh[u * G3 + g];
        if (g < 256) {
            bias[g] = bi + bh;          // r,z: biases fold into the summed gate
        } else {
            bias[g]       = bi;         // [256:384) xn bias
            bias[g + 128] = bh;         // [384:512) hn bias
        }
    }
    __syncthreads();
    // All mbarriers initialized in both CTAs before any cross-CTA arrival /
    // multicast commit; also orders TMEM alloc across the pair.
    CLUSTER_SYNC();

    uint32_t tmem_base;
    asm volatile("ld.shared.b32 %0, [%1];"
                 : "=r"(tmem_base) : "r"(smem_base + SMEM_TMEMPTR));

    // ---------------- pipelined mainloop: 8 chunks, 4 stages -----------------
    for (int ch = 0; ch < 8; ch++) {
        const int ph = ch >> 2;          // 0: x-side, 1: h-side
        const int cc = ch & 3;           // K32 chunk within side
        const int k0 = cc * 32;
        const int s  = ch & 3;           // stage
        const int stage = SMEM_STAGES + s * SMEM_STAGE_SZ;
        const uint32_t done_mbar  = smem_base + SMEM_DONE  + s * 8;
        const uint32_t ready_mbar = smem_base + SMEM_READY + s * 8;

        const float* asrc = ph ? hidden : inputs;
        const __nv_bfloat16* wh = ph ? g_whh_hi : g_wih_hi;
        const __nv_bfloat16* wl = ph ? g_whh_lo : g_wih_lo;

        // Backpressure: stage reused at ch-4; wait for its MMA commit.
        if (ch >= 4) MBARRIER_WAIT_PARITY(done_mbar, ((ch >> 2) + 1) & 1);

        // B tile via cp.async (this CTA's N/2 split: 3 N-tiles x 64 rows x 64B)
        #pragma unroll
        for (int i = 0; i < 3; i++) {
            const int q  = tid + i * 256;          // [0,768)
            const int lr = q >> 2;                 // local row 0..191
            const int nt = lr >> 6;
            const int g  = nt * 128 + (int)rank * 64 + (lr & 63);
            const int ce = (q & 3) << 3;           // element col (x8)
            const size_t gi = (((size_t)u * G3) + g) * I_DIM + k0 + ce;
            const uint32_t off = SMEM_SWIZZLE_64B((uint32_t)(lr * 64 + (q & 3) * 16));
            cp_async_16(smem_base + stage + OFF_B_HI + off, wh + gi);
            cp_async_16(smem_base + stage + OFF_B_LO + off, wl + gi);
        }
        asm volatile("cp.async.commit_group;" ::: "memory");

        // A tile: 128 rows x 32 fp32 -> bf16 hi/lo split, SW64 swizzled
        #pragma unroll
        for (int i = 0; i < 4; i++) {
            const int q = tid + i * 256;           // [0,1024)
            const int row  = q >> 3;
            const int colf = (q & 7) << 2;
            const float4 v = *(const float4*)(asrc +
                (((size_t)(b0 + row)) * U_DIM + u) * I_DIM + k0 + colf);
            __nv_bfloat162 h0 = __float22bfloat162_rn(make_float2(v.x, v.y));
            __nv_bfloat162 h1 = __float22bfloat162_rn(make_float2(v.z, v.w));
            float2 r0 = make_float2(v.x - __bfloat162float(h0.x),
                                    v.y - __bfloat162float(h0.y));
            float2 r1 = make_float2(v.z - __bfloat162float(h1.x),
                                    v.w - __bfloat162float(h1.y));
            __nv_bfloat162 l0 = __float22bfloat162_rn(r0);
            __nv_bfloat162 l1 = __float22bfloat162_rn(r1);
            const uint32_t off = SMEM_SWIZZLE_64B((uint32_t)(row * 64 + colf * 2));
            *(uint2*)(smem + stage + OFF_A_HI + off) =
                make_uint2(*(uint32_t*)&h0, *(uint32_t*)&h1);
            *(uint2*)(smem + stage + OFF_A_LO + off) =
                make_uint2(*(uint32_t*)&l0, *(uint32_t*)&l1);
        }

        asm volatile("cp.async.wait_group 0;" ::: "memory");
        FENCE_PROXY_ASYNC_SHARED_CTA();
        __syncthreads();
        // Announce this CTA's tiles to the leader (rank 0) for this stage.
        if (tid == 0) MBARRIER_ARRIVE_CLUSTER(ready_mbar, 0);

        // Leader: wait both CTAs' tiles, then issue cg2 MMAs.
        // 3 split terms x 2 K16 steps x 3 N128 tiles = 18 dispatches, M=256.
        if (rank == 0 && wid == 0) {
            if (elect_one_pred()) {
                MBARRIER_WAIT_PARITY_CLU(ready_mbar, (ch >> 2) & 1);
                const uint32_t sb = smem_base + stage;
                const uint64_t adh = MAKE_SMEM_DESC64(sb + OFF_A_HI);
                const uint64_t adl = MAKE_SMEM_DESC64(sb + OFF_A_LO);
                const uint64_t bdh = MAKE_SMEM_DESC64(sb + OFF_B_HI);
                const uint64_t bdl = MAKE_SMEM_DESC64(sb + OFF_B_LO);
                #pragma unroll
                for (int term = 0; term < 3; term++) {
                    const uint64_t ad = (term == 2) ? adl : adh;
                    const uint64_t bd = (term == 1) ? bdl : bdh;
                    #pragma unroll
                    for (int ks = 0; ks < 2; ks++) {
                        #pragma unroll
                        for (int nt = 0; nt < 3; nt++) {
                            const uint32_t dcol =
                                (ph == 1 && nt == 2) ? 384u : (uint32_t)(nt * 128);
                            const uint32_t first =
                                (cc == 0 && term == 0 && ks == 0) ? 1u : 0u;
                            uint32_t en;
                            if (ph == 0)
                                en = first ? 0u : 1u;           // r,z,xn first touch
                            else
                                en = (nt < 2) ? 1u : (first ? 0u : 1u); // hn first
                            mma_f16_ss_cg2(tmem_base + dcol,
                                           ad + ks * 2,
                                           bd + nt * 256 + ks * 2,
                                           IDESC_CG2, en);
                        }
                    }
                }
                TCGEN05_COMMIT_MCAST_CG2(done_mbar, 0x3);
            }
        }
    }

    // Final commits: each stage committed twice (parity 1).
    #pragma unroll
    for (int s = 0; s < 4; s++)
        MBARRIER_WAIT_PARITY(smem_base + SMEM_DONE + s * 8, 1);
    TCGEN05_FENCE_AFTER();

    // ---------------- epilogue: TMEM -> GRU elementwise -> GMEM --------------
    // Warps 0-3 cols [0,64), warps 4-7 cols [64,128); TMEM subpart = wid & 3.
    const int row = (wid & 3) * 32 + lid;
    const int c0  = (wid >> 2) * 64;
    const float* hrow = hidden + (((size_t)(b0 + row)) * U_DIM + u) * H_DIM;
    float*       orow = out    + (((size_t)(b0 + row)) * U_DIM + u) * H_DIM;

    for (int cb = c0; cb < c0 + 64; cb += 16) {
        uint32_t rr[16], zz[16], xn[16], hn[16];
        TCGEN05_LD_32X32B_X16(rr, tmem_base + cb);
        TCGEN05_LD_32X32B_X16(zz, tmem_base + 128 + cb);
        TCGEN05_LD_32X32B_X16(xn, tmem_base + 256 + cb);
        TCGEN05_LD_32X32B_X16(hn, tmem_base + 384 + cb);
        TCGEN05_WAIT_LD();

        float4 hv[4];
        const float4* hp = (const float4*)(hrow + cb);
        hv[0] = hp[0]; hv[1] = hp[1]; hv[2] = hp[2]; hv[3] = hp[3];
        const float* hvf = (const float*)hv;

        float res[16];
        #pragma unroll
        for (int j = 0; j < 16; j++) {
            const int c = cb + j;
            const float vr = __uint_as_float(rr[j]) + bias[c];
            const float vz = __uint_as_float(zz[j]) + bias[128 + c];
            const float r  = 1.f / (1.f + __expf(-vr));
            const float z  = 1.f / (1.f + __expf(-vz));
            const float vn = __uint_as_float(xn[j]) + bias[256 + c]
                           + r * (__uint_as_float(hn[j]) + bias[384 + c]);
            const float n  = tanhf(vn);
            res[j] = (1.f - z) * n + z * hvf[j];
        }
        TCGEN05_FENCE_BEFORE();
        float4* op = (float4*)(orow + cb);
        op[0] = ((float4*)res)[0];
        op[1] = ((float4*)res)[1];
        op[2] = ((float4*)res)[2];
        op[3] = ((float4*)res)[3];
    }

    __syncthreads();
    CLUSTER_SYNC();                 // both CTAs done with TMEM + peer smem
    if (wid == 0) {
        TCGEN05_DEALLOC_CG2(tmem_base, 512);
    }
    CLUSTER_SYNC();

#else  // ---------------- fallback: plain fp32 FFMA (non-sm_103a targets) ----
    // Correct but slow; only executes if the runtime ever JITs the plain
    // compute_103 PTX instead of using the sm_103a cubin.
    float* xs = (float*)smem;              // 128 x 128
    float* hs = xs + 128 * 128;            // 128 x 128
    for (int q = tid; q < 128 * 128; q += 256) {
        const int row = q >> 7, col = q & 127;
        const size_t base = (((size_t)(b0 + row)) * U_DIM + u) * I_DIM + col;
        xs[q] = inputs[base];
        hs[q] = hidden[base];
    }
    __syncthreads();

    if (tid < 128) {
        const float* xr_ = xs + tid * 128;
        const float* hr_ = hs + tid * 128;
        float* orow = out + (((size_t)(b0 + tid)) * U_DIM + u) * H_DIM;

        for (int c = 0; c < H_DIM; c++) {
            float axr = b_ih[u * G3 + c],       ahr = b_hh[u * G3 + c];
            float axz = b_ih[u * G3 + 128 + c], ahz = b_hh[u * G3 + 128 + c];
            float axn = b_ih[u * G3 + 256 + c], ahn = b_hh[u * G3 + 256 + c];
            const float* wir = w_ih + (((size_t)u * G3) + c) * I_DIM;
            const float* whr = w_hh + (((size_t)u * G3) + c) * I_DIM;
            for (int k = 0; k < I_DIM; k++) {
                const float xv = xr_[k], hv = hr_[k];
                axr += xv * wir[k];
                axz += xv * wir[128 * I_DIM + k];
                axn += xv * wir[256 * I_DIM + k];
                ahr += hv * whr[k];
                ahz += hv * whr[128 * I_DIM + k];
                ahn += hv * whr[256 * I_DIM + k];
            }
            const float r = 1.f / (1.f + expf(-(axr + ahr)));
            const float z = 1.f / (1.f + expf(-(axz + ahz)));
            const float n = tanhf(axn + r * ahn);
            orow[c] = (1.f - z) * n + z * hr_[c];
        }
    }
#endif
}

// ============================================================================
// kernel_launch — graph-capturable, allocation-free
// ============================================================================
extern "C" void kernel_launch(void* const* d_in, const int* in_sizes, int n_in,
                              void* d_out, int out_size) {
    const float* inputs = (const float*)d_in[0];
    const float* hidden = (const float*)d_in[1];
    const float* w_ih   = (const float*)d_in[2];
    const float* w_hh   = (const float*)d_in[3];
    const float* b_ih   = (const float*)d_in[4];
    const float* b_hh   = (const float*)d_in[5];
    float* out = (float*)d_out;

    const int B = in_sizes[0] / (U_DIM * I_DIM);   // 8192

    gru_prep<<<(W_ELEMS + 255) / 256, 256>>>(w_ih, w_hh);

    cudaFuncSetAttribute(gru_main,
                         cudaFuncAttributeMaxDynamicSharedMemorySize, SMEM_TOTAL);
    gru_main<<<dim3(B / 128, U_DIM), 256, SMEM_TOTAL>>>(
        inputs, hidden, w_ih, w_hh, b_ih, b_hh, out);
}

// round 13
// speedup vs baseline: 1.0098x; 1.0098x over previous
#include <cuda_runtime.h>
#include <cuda_bf16.h>
#include <cstdint>

// ============================================================================
// Arch gating: tcgen05/TMEM are sm_103a ("arch-specific") features. The
// harness also compiles a plain compute_103 stage, which must not see any
// tcgen05 PTX. HAS_TC selects the real tensor-core path only on the
// arch-specific device pass; all other passes get a correct FFMA fallback.
// ============================================================================
#if defined(__CUDA_ARCH__) && \
    (defined(__CUDA_ARCH_FEAT_SM103_ALL) || defined(__CUDA_ARCH_FEAT_SM100_ALL) || \
     defined(__CUDA_ARCH_SPECIFIC__) || defined(__CUDA_ARCH_FAMILY_SPECIFIC__))
#define HAS_TC 1
#else
#define HAS_TC 0
#endif

// ============================================================================
// Problem constants: B=8192 (derived at launch), U=16, I=H=128, 3H=384 gates
// ============================================================================
#define U_DIM 16
#define I_DIM 128
#define H_DIM 128
#define G3    384
#define W_ELEMS (U_DIM * G3 * I_DIM)   // 786432 per weight matrix

// Pre-split weights (fp32 -> bf16 hi + bf16 lo), filled by prep kernel.
__device__ __nv_bfloat16 g_wih_hi[W_ELEMS];
__device__ __nv_bfloat16 g_wih_lo[W_ELEMS];
__device__ __nv_bfloat16 g_whh_hi[W_ELEMS];
__device__ __nv_bfloat16 g_whh_lo[W_ELEMS];

// ============================================================================
// PTX helpers
// ============================================================================
__device__ __forceinline__ uint32_t elect_one_pred() {
    uint32_t pred;
    asm volatile(
        "{\n\t"
        ".reg .pred p;\n\t"
        "elect.sync _|p, 0xFFFFFFFF;\n\t"
        "selp.b32 %0, 1, 0, p;\n\t"
        "}"
        : "=r"(pred));
    return pred;
}

__device__ __forceinline__ uint32_t smem_to_u32(const void* smem_ptr) {
    uint32_t addr;
    asm("{ .reg .u64 tmp; cvta.to.shared.u64 tmp, %1; cvt.u32.u64 %0, tmp; }"
        : "=r"(addr) : "l"(smem_ptr));
    return addr;
}

__device__ __forceinline__ uint32_t cluster_rank() {
    uint32_t r;
    asm("mov.u32 %0, %%cluster_ctarank;" : "=r"(r));
    return r;
}

#define CLUSTER_SYNC() do { \
    asm volatile("barrier.cluster.arrive.aligned;" ::: "memory"); \
    asm volatile("barrier.cluster.wait.aligned;" ::: "memory"); \
} while (0)

// SW64 swizzle: atom = 8 rows x 64 bytes
#define SMEM_SWIZZLE_64B(byte_offset) \
    ((byte_offset) ^ (((byte_offset) >> 3) & 0x30))

// SW64 smem descriptor: layout=4, version=1 (Blackwell), SBO=32 (512B per
// 8-row group), LBO=1 (16B inner stride). Rows are 64B wide.
static constexpr uint64_t SMEM_DESC_BASE_SW64 =
    (uint64_t(4)  << 61)
    | (uint64_t(1) << 46)
    | (uint64_t(32) << 32)
    | (uint64_t(1) << 16);

#define MAKE_SMEM_DESC64(base_addr) \
    (SMEM_DESC_BASE_SW64 | ((uint64_t)((base_addr) >> 4) & 0x3FFF))

#define TCGEN05_ALLOC_CG2(smem_result_addr, nCols) \
    asm volatile( \
        "tcgen05.alloc.cta_group::2.sync.aligned.shared::cta.b32 [%0], %1;" \
        :: "r"((uint32_t)(smem_result_addr)), "r"((uint32_t)(nCols)) \
        : "memory")

#define TCGEN05_DEALLOC_CG2(tmem_addr, nCols) \
    asm volatile( \
        "tcgen05.dealloc.cta_group::2.sync.aligned.b32 %0, %1;" \
        :: "r"(tmem_addr), "r"((uint32_t)(nCols)))

#define TCGEN05_RELINQUISH_CG2() \
    asm volatile("tcgen05.relinquish_alloc_permit.cta_group::2.sync.aligned;")

#define TCGEN05_COMMIT_MCAST_CG2(mbar_smem_addr, cta_mask) \
    asm volatile( \
        "tcgen05.commit.cta_group::2.mbarrier::arrive::one.shared::cluster.multicast::cluster.b64 [%0], %1;" \
        :: "r"((uint32_t)(mbar_smem_addr)), "h"((uint16_t)(cta_mask)) \
        : "memory")

#define TCGEN05_FENCE_AFTER() \
    asm volatile("tcgen05.fence::after_thread_sync;" ::: "memory")

#define TCGEN05_FENCE_BEFORE() \
    asm volatile("tcgen05.fence::before_thread_sync;" ::: "memory")

#define TCGEN05_WAIT_LD() \
    asm volatile("tcgen05.wait::ld.sync.aligned;" ::: "memory")

#define FENCE_PROXY_ASYNC_SHARED_CTA() \
    asm volatile("fence.proxy.async.shared::cta;" ::: "memory")

#define MBARRIER_INIT(mbar_smem_addr, count) \
    asm volatile( \
        "mbarrier.init.shared.b64 [%0], %1;" \
        :: "r"((uint32_t)(mbar_smem_addr)), "r"((uint32_t)(count)) \
        : "memory")

// Arrive (release.cluster) on the mbarrier at the same SMEM offset in CTA
// `target_rank` of this cluster.
#define MBARRIER_ARRIVE_CLUSTER(local_mbar_addr, target_rank) \
    asm volatile( \
        "{\n\t" \
        ".reg .b32 remAddr32;\n\t" \
        "mapa.shared::cluster.u32 remAddr32, %0, %1;\n\t" \
        "mbarrier.arrive.release.cluster.shared::cluster.b64 _, [remAddr32];\n\t" \
        "}" \
        :: "r"((uint32_t)(local_mbar_addr)), "r"((uint32_t)(target_rank)) \
        : "memory")

#define MBARRIER_WAIT_PARITY_SC(mbar_smem_addr, phase_parity, SCOPE) do { \
    uint32_t _mbar = (uint32_t)(mbar_smem_addr); \
    uint32_t _parity = (uint32_t)(phase_parity); \
    uint32_t _done; \
    asm volatile( \
        "{\n\t" \
        ".reg .pred p;\n\t" \
        "mbarrier.try_wait.parity.acquire." SCOPE ".shared::cta.b64 p, [%1], %2;\n\t" \
        "selp.b32 %0, 1, 0, p;\n\t" \
        "}" \
        : "=r"(_done) : "r"(_mbar), "r"(_parity) : "memory"); \
    if (!_done) { \
        asm volatile( \
            "{\n\t" \
            ".reg .pred P1;\n\t" \
            "WAIT_LOOP_%=:\n\t" \
            "mbarrier.try_wait.parity.acquire." SCOPE ".shared::cta.b64 P1, [%0], %1, 0x989680;\n\t" \
            "@P1 bra.uni WAIT_DONE_%=;\n\t" \
            "bra.uni WAIT_LOOP_%=;\n\t" \
            "WAIT_DONE_%=:\n\t" \
            "}" \
            :: "r"(_mbar), "r"(_parity) : "memory"); \
    } \
} while(0)

#define MBARRIER_WAIT_PARITY(mbar, par)     MBARRIER_WAIT_PARITY_SC(mbar, par, "cta")
#define MBARRIER_WAIT_PARITY_CLU(mbar, par) MBARRIER_WAIT_PARITY_SC(mbar, par, "cluster")

#define TCGEN05_LD_32X32B_X16(r, tmem_addr) \
    asm volatile( \
        "tcgen05.ld.sync.aligned.32x32b.x16.b32 " \
        "{%0, %1, %2, %3, %4, %5, %6, %7, " \
        " %8, %9, %10, %11, %12, %13, %14, %15}, [%16];" \
        : "=r"((r)[0]),  "=r"((r)[1]),  "=r"((r)[2]),  "=r"((r)[3]), \
          "=r"((r)[4]),  "=r"((r)[5]),  "=r"((r)[6]),  "=r"((r)[7]), \
          "=r"((r)[8]),  "=r"((r)[9]),  "=r"((r)[10]), "=r"((r)[11]), \
          "=r"((r)[12]), "=r"((r)[13]), "=r"((r)[14]), "=r"((r)[15]) \
        : "r"(tmem_addr))

#if HAS_TC
// SS-mode cg2 bf16 MMA (kind::f16), fp32 accumulate in TMEM. M=256 across the
// CTA pair: A rows 128*rank..+128 from each CTA's smem at the same offset;
// B split N/2 (64 rows) per CTA at the same offset.
__device__ __forceinline__ void mma_f16_ss_cg2(uint32_t d_tmem, uint64_t a_desc,
                                               uint64_t b_desc, uint32_t idesc,
                                               uint32_t en) {
    asm volatile(
        "{\n\t"
        ".reg .pred p;\n\t"
        "setp.ne.u32 p, %5, 0;\n\t"
        "tcgen05.mma.cta_group::2.kind::f16 [%0], %1, %2, %3, "
        "{%4, %4, %4, %4, %4, %4, %4, %4}, p;\n\t"
        "}"
        :: "r"(d_tmem), "l"(a_desc), "l"(b_desc), "r"(idesc), "r"(0u), "r"(en)
        : "memory");
}

// 16-byte async copy, L2-only (.cg): streamed weights have no L1 reuse.
__device__ __forceinline__ void cp_async_16(uint32_t saddr, const void* gptr) {
    asm volatile(
        "{\n\t"
        ".reg .u64 g;\n\t"
        "cvta.to.global.u64 g, %1;\n\t"
        "cp.async.cg.shared.global [%0], [g], 16;\n\t"
        "}"
        :: "r"(saddr), "l"(gptr) : "memory");
}
#endif

// ============================================================================
// Shared memory layout. K-chunk = 32 (64B rows, SW64). FOUR pipeline stages.
// Per stage: A_HI 8KB | A_LO 8KB | B_HI 12KB | B_LO 12KB = 40KB.
// (B is split N/2 per CTA under cg2: 3 N-tiles x 64 rows x 64B.)
// ============================================================================
static constexpr int SMEM_TMEMPTR   = 0;
static constexpr int SMEM_DONE      = 8;    // 4 x 8B: per-stage "mma done"
static constexpr int SMEM_READY     = 40;   // 4 x 8B: per-stage "tiles ready" (leader's used)
static constexpr int SMEM_BIAS      = 128;  // 512 floats
static constexpr int SMEM_STAGE_SZ  = 40960;
static constexpr int SMEM_STAGES    = 4096;
static constexpr int OFF_A_HI       = 0;      // 128 x 64B = 8 KB
static constexpr int OFF_A_LO       = 8192;   // 8 KB
static constexpr int OFF_B_HI       = 16384;  // 192 x 64B = 12 KB
static constexpr int OFF_B_LO       = 28672;  // 12 KB
static constexpr int SMEM_TOTAL     = SMEM_STAGES + 4 * SMEM_STAGE_SZ; // 167936

// idesc kind::f16 cg2: dtype=F32, atype=btype=BF16, N=128, M=256
static constexpr uint32_t IDESC_CG2 =
    (1u << 4) | (1u << 7) | (1u << 10) | ((128u / 8) << 17) | ((256u / 16) << 24);

// ============================================================================
// Prep kernel: split fp32 weights into bf16 hi/lo pairs
// ============================================================================
__global__ void __launch_bounds__(256) gru_prep(const float* __restrict__ w_ih,
                                                const float* __restrict__ w_hh) {
    int i = blockIdx.x * 256 + threadIdx.x;
    if (i >= W_ELEMS) return;
    float v = w_ih[i];
    __nv_bfloat16 h = __float2bfloat16(v);
    g_wih_hi[i] = h;
    g_wih_lo[i] = __float2bfloat16(v - __bfloat162float(h));
    v = w_hh[i];
    h = __float2bfloat16(v);
    g_whh_hi[i] = h;
    g_whh_lo[i] = __float2bfloat16(v - __bfloat162float(h));
}

// ============================================================================
// Main fused GRU kernel. Cluster of 2 CTAs = (u, 256-row batch tile); each
// CTA owns 128 rows. 256 threads. TMEM D (per CTA, its own 128 rows):
// [0:128)=r_sum [128:256)=z_sum [256:384)=xn [384:512)=hn.
// 8 chunks (2 sides x 4 K32-chunks), 4 smem stages, cg2 MMA issued by rank 0.
// ============================================================================
__global__ void __launch_bounds__(256, 1) __cluster_dims__(2, 1, 1)
gru_main(
    const float* __restrict__ inputs,
    const float* __restrict__ hidden,
    const float* __restrict__ w_ih,
    const float* __restrict__ w_hh,
    const float* __restrict__ b_ih,
    const float* __restrict__ b_hh,
    float* __restrict__ out)
{
    extern __shared__ __align__(1024) char smem[];
    const int tid = threadIdx.x;
    const int u   = blockIdx.y;
    const int b0  = blockIdx.x * 128;        // this CTA's 128 batch rows

#if HAS_TC
    const uint32_t smem_base = smem_to_u32(smem);
    const int wid  = tid >> 5;
    const int lid  = tid & 31;
    const uint32_t rank = cluster_rank();    // == blockIdx.x & 1

    if (wid == 0) {
        TCGEN05_ALLOC_CG2(smem_base + SMEM_TMEMPTR, 512);
        TCGEN05_RELINQUISH_CG2();
    }
    if (tid == 0) {
        #pragma unroll
        for (int s = 0; s < 4; s++) {
            MBARRIER_INIT(smem_base + SMEM_DONE  + s * 8, 1);  // tcgen05 commit
            MBARRIER_INIT(smem_base + SMEM_READY + s * 8, 2);  // 1 arrive per CTA
        }
    }

    float* bias = (float*)(smem + SMEM_BIAS);
    for (int g = tid; g < G3; g += 256) {
        float bi = b_ih[u * G3 + g];
        float bh = b_hh[u * G3 + g];
        if (g < 256) {
            bias[g] = bi + bh;          // r,z: biases fold into the summed gate
        } else {
            bias[g]       = bi;         // [256:384) xn bias
            bias[g + 128] = bh;         // [384:512) hn bias
        }
    }
    __syncthreads();
    // All mbarriers initialized in both CTAs before any cross-CTA arrival /
    // multicast commit; also orders TMEM alloc across the pair.
    CLUSTER_SYNC();

    uint32_t tmem_base;
    asm volatile("ld.shared.b32 %0, [%1];"
                 : "=r"(tmem_base) : "r"(smem_base + SMEM_TMEMPTR));

    // ---------------- pipelined mainloop: 8 chunks, 4 stages -----------------
    for (int ch = 0; ch < 8; ch++) {
        const int ph = ch >> 2;          // 0: x-side, 1: h-side
        const int cc = ch & 3;           // K32 chunk within side
        const int k0 = cc * 32;
        const int s  = ch & 3;           // stage
        const int stage = SMEM_STAGES + s * SMEM_STAGE_SZ;
        const uint32_t done_mbar  = smem_base + SMEM_DONE  + s * 8;
        const uint32_t ready_mbar = smem_base + SMEM_READY + s * 8;

        const float* asrc = ph ? hidden : inputs;
        const __nv_bfloat16* wh = ph ? g_whh_hi : g_wih_hi;
        const __nv_bfloat16* wl = ph ? g_whh_lo : g_wih_lo;

        // Backpressure: stage reused at ch-4; wait for its MMA commit.
        if (ch >= 4) MBARRIER_WAIT_PARITY(done_mbar, ((ch >> 2) + 1) & 1);

        // B tile via cp.async (this CTA's N/2 split: 3 N-tiles x 64 rows x 64B)
        #pragma unroll
        for (int i = 0; i < 3; i++) {
            const int q  = tid + i * 256;          // [0,768)
            const int lr = q >> 2;                 // local row 0..191
            const int nt = lr >> 6;
            const int g  = nt * 128 + (int)rank * 64 + (lr & 63);
            const int ce = (q & 3) << 3;           // element col (x8)
            const size_t gi = (((size_t)u * G3) + g) * I_DIM + k0 + ce;
            const uint32_t off = SMEM_SWIZZLE_64B((uint32_t)(lr * 64 + (q & 3) * 16));
            cp_async_16(smem_base + stage + OFF_B_HI + off, wh + gi);
            cp_async_16(smem_base + stage + OFF_B_LO + off, wl + gi);
        }
        asm volatile("cp.async.commit_group;" ::: "memory");

        // A tile: 128 rows x 32 fp32 -> bf16 hi/lo split, SW64 swizzled
        #pragma unroll
        for (int i = 0; i < 4; i++) {
            const int q = tid + i * 256;           // [0,1024)
            const int row  = q >> 3;
            const int colf = (q & 7) << 2;
            const float4 v = *(const float4*)(asrc +
                (((size_t)(b0 + row)) * U_DIM + u) * I_DIM + k0 + colf);
            __nv_bfloat162 h0 = __float22bfloat162_rn(make_float2(v.x, v.y));
            __nv_bfloat162 h1 = __float22bfloat162_rn(make_float2(v.z, v.w));
            float2 r0 = make_float2(v.x - __bfloat162float(h0.x),
                                    v.y - __bfloat162float(h0.y));
            float2 r1 = make_float2(v.z - __bfloat162float(h1.x),
                                    v.w - __bfloat162float(h1.y));
            __nv_bfloat162 l0 = __float22bfloat162_rn(r0);
            __nv_bfloat162 l1 = __float22bfloat162_rn(r1);
            const uint32_t off = SMEM_SWIZZLE_64B((uint32_t)(row * 64 + colf * 2));
            *(uint2*)(smem + stage + OFF_A_HI + off) =
                make_uint2(*(uint32_t*)&h0, *(uint32_t*)&h1);
            *(uint2*)(smem + stage + OFF_A_LO + off) =
                make_uint2(*(uint32_t*)&l0, *(uint32_t*)&l1);
        }

        asm volatile("cp.async.wait_group 0;" ::: "memory");
        FENCE_PROXY_ASYNC_SHARED_CTA();
        __syncthreads();
        // Announce this CTA's tiles to the leader (rank 0) for this stage.
        if (tid == 0) MBARRIER_ARRIVE_CLUSTER(ready_mbar, 0);

        // Leader: wait both CTAs' tiles, then issue cg2 MMAs.
        // 3 split terms x 2 K16 steps x 3 N128 tiles = 18 dispatches, M=256.
        if (rank == 0 && wid == 0) {
            if (elect_one_pred()) {
                MBARRIER_WAIT_PARITY_CLU(ready_mbar, (ch >> 2) & 1);
                const uint32_t sb = smem_base + stage;
                const uint64_t adh = MAKE_SMEM_DESC64(sb + OFF_A_HI);
                const uint64_t adl = MAKE_SMEM_DESC64(sb + OFF_A_LO);
                const uint64_t bdh = MAKE_SMEM_DESC64(sb + OFF_B_HI);
                const uint64_t bdl = MAKE_SMEM_DESC64(sb + OFF_B_LO);
                #pragma unroll
                for (int term = 0; term < 3; term++) {
                    const uint64_t ad = (term == 2) ? adl : adh;
                    const uint64_t bd = (term == 1) ? bdl : bdh;
                    #pragma unroll
                    for (int ks = 0; ks < 2; ks++) {
                        #pragma unroll
                        for (int nt = 0; nt < 3; nt++) {
                            const uint32_t dcol =
                                (ph == 1 && nt == 2) ? 384u : (uint32_t)(nt * 128);
                            const uint32_t first =
                                (cc == 0 && term == 0 && ks == 0) ? 1u : 0u;
                            uint32_t en;
                            if (ph == 0)
                                en = first ? 0u : 1u;           // r,z,xn first touch
                            else
                                en = (nt < 2) ? 1u : (first ? 0u : 1u); // hn first
                            mma_f16_ss_cg2(tmem_base + dcol,
                                           ad + ks * 2,
                                           bd + nt * 256 + ks * 2,
                                           IDESC_CG2, en);
                        }
                    }
                }
                TCGEN05_COMMIT_MCAST_CG2(done_mbar, 0x3);
            }
        }
    }

    // Final commits: each stage committed twice (parity 1).
    #pragma unroll
    for (int s = 0; s < 4; s++)
        MBARRIER_WAIT_PARITY(smem_base + SMEM_DONE + s * 8, 1);
    TCGEN05_FENCE_AFTER();

    // ---------------- epilogue: TMEM -> GRU elementwise -> GMEM --------------
    // Warps 0-3 cols [0,64), warps 4-7 cols [64,128); TMEM subpart = wid & 3.
    const int row = (wid & 3) * 32 + lid;
    const int c0  = (wid >> 2) * 64;
    const float* hrow = hidden + (((size_t)(b0 + row)) * U_DIM + u) * H_DIM;
    float*       orow = out    + (((size_t)(b0 + row)) * U_DIM + u) * H_DIM;

    for (int cb = c0; cb < c0 + 64; cb += 16) {
        uint32_t rr[16], zz[16], xn[16], hn[16];
        TCGEN05_LD_32X32B_X16(rr, tmem_base + cb);
        TCGEN05_LD_32X32B_X16(zz, tmem_base + 128 + cb);
        TCGEN05_LD_32X32B_X16(xn, tmem_base + 256 + cb);
        TCGEN05_LD_32X32B_X16(hn, tmem_base + 384 + cb);
        TCGEN05_WAIT_LD();

        float4 hv[4];
        const float4* hp = (const float4*)(hrow + cb);
        hv[0] = hp[0]; hv[1] = hp[1]; hv[2] = hp[2]; hv[3] = hp[3];
        const float* hvf = (const float*)hv;

        float res[16];
        #pragma unroll
        for (int j = 0; j < 16; j++) {
            const int c = cb + j;
            const float vr = __uint_as_float(rr[j]) + bias[c];
            const float vz = __uint_as_float(zz[j]) + bias[128 + c];
            const float r  = 1.f / (1.f + __expf(-vr));
            const float z  = 1.f / (1.f + __expf(-vz));
            const float vn = __uint_as_float(xn[j]) + bias[256 + c]
                           + r * (__uint_as_float(hn[j]) + bias[384 + c]);
            const float n  = tanhf(vn);
            res[j] = (1.f - z) * n + z * hvf[j];
        }
        TCGEN05_FENCE_BEFORE();
        float4* op = (float4*)(orow + cb);
        op[0] = ((float4*)res)[0];
        op[1] = ((float4*)res)[1];
        op[2] = ((float4*)res)[2];
        op[3] = ((float4*)res)[3];
    }

    __syncthreads();
    CLUSTER_SYNC();                 // both CTAs done with TMEM + peer smem
    if (wid == 0) {
        TCGEN05_DEALLOC_CG2(tmem_base, 512);
    }
    CLUSTER_SYNC();

#else  // ---------------- fallback: plain fp32 FFMA (non-sm_103a targets) ----
    // Correct but slow; only executes if the runtime ever JITs the plain
    // compute_103 PTX instead of using the sm_103a cubin.
    float* xs = (float*)smem;              // 128 x 128
    float* hs = xs + 128 * 128;            // 128 x 128
    for (int q = tid; q < 128 * 128; q += 256) {
        const int row = q >> 7, col = q & 127;
        const size_t base = (((size_t)(b0 + row)) * U_DIM + u) * I_DIM + col;
        xs[q] = inputs[base];
        hs[q] = hidden[base];
    }
    __syncthreads();

    if (tid < 128) {
        const float* xr_ = xs + tid * 128;
        const float* hr_ = hs + tid * 128;
        float* orow = out + (((size_t)(b0 + tid)) * U_DIM + u) * H_DIM;

        for (int c = 0; c < H_DIM; c++) {
            float axr = b_ih[u * G3 + c],       ahr = b_hh[u * G3 + c];
            float axz = b_ih[u * G3 + 128 + c], ahz = b_hh[u * G3 + 128 + c];
            float axn = b_ih[u * G3 + 256 + c], ahn = b_hh[u * G3 + 256 + c];
            const float* wir = w_ih + (((size_t)u * G3) + c) * I_DIM;
            const float* whr = w_hh + (((size_t)u * G3) + c) * I_DIM;
            for (int k = 0; k < I_DIM; k++) {
                const float xv = xr_[k], hv = hr_[k];
                axr += xv * wir[k];
                axz += xv * wir[128 * I_DIM + k];
                axn += xv * wir[256 * I_DIM + k];
                ahr += hv * whr[k];
                ahz += hv * whr[128 * I_DIM + k];
                ahn += hv * whr[256 * I_DIM + k];
            }
            const float r = 1.f / (1.f + expf(-(axr + ahr)));
            const float z = 1.f / (1.f + expf(-(axz + ahz)));
            const float n = tanhf(axn + r * ahn);
            orow[c] = (1.f - z) * n + z * hr_[c];
        }
    }
#endif
}

// ============================================================================
// kernel_launch — graph-capturable, allocation-free
// ============================================================================
extern "C" void kernel_launch(void* const* d_in, const int* in_sizes, int n_in,
                              void* d_out, int out_size) {
    const float* inputs = (const float*)d_in[0];
    const float* hidden = (const float*)d_in[1];
    const float* w_ih   = (const float*)d_in[2];
    const float* w_hh   = (const float*)d_in[3];
    const float* b_ih   = (const float*)d_in[4];
    const float* b_hh   = (const float*)d_in[5];
    float* out = (float*)d_out;

    const int B = in_sizes[0] / (U_DIM * I_DIM);   // 8192

    gru_prep<<<(W_ELEMS + 255) / 256, 256>>>(w_ih, w_hh);

    cudaFuncSetAttribute(gru_main,
                         cudaFuncAttributeMaxDynamicSharedMemorySize, SMEM_TOTAL);
    gru_main<<<dim3(B / 128, U_DIM), 256, SMEM_TOTAL>>>(
        inputs, hidden, w_ih, w_hh, b_ih, b_hh, out);
}

// round 14
// speedup vs baseline: 1.3341x; 1.3212x over previous
#include <cuda_runtime.h>
#include <cuda_bf16.h>
#include <cstdint>

// ============================================================================
// Arch gating: tcgen05/TMEM are sm_103a ("arch-specific") features. The
// harness also compiles a plain compute_103 stage, which must not see any
// tcgen05 PTX. HAS_TC selects the real tensor-core path only on the
// arch-specific device pass; all other passes get a correct FFMA fallback.
// ============================================================================
#if defined(__CUDA_ARCH__) && \
    (defined(__CUDA_ARCH_FEAT_SM103_ALL) || defined(__CUDA_ARCH_FEAT_SM100_ALL) || \
     defined(__CUDA_ARCH_SPECIFIC__) || defined(__CUDA_ARCH_FAMILY_SPECIFIC__))
#define HAS_TC 1
#else
#define HAS_TC 0
#endif

// ============================================================================
// Problem constants: B=8192 (derived at launch), U=16, I=H=128, 3H=384 gates
// ============================================================================
#define U_DIM 16
#define I_DIM 128
#define H_DIM 128
#define G3    384
#define W_ELEMS (U_DIM * G3 * I_DIM)   // 786432 per weight matrix

// Pre-split weights (fp32 -> bf16 hi + bf16 lo), filled by prep kernel.
__device__ __nv_bfloat16 g_wih_hi[W_ELEMS];
__device__ __nv_bfloat16 g_wih_lo[W_ELEMS];
__device__ __nv_bfloat16 g_whh_hi[W_ELEMS];
__device__ __nv_bfloat16 g_whh_lo[W_ELEMS];

// ============================================================================
// PTX helpers
// ============================================================================
__device__ __forceinline__ uint32_t elect_one_pred() {
    uint32_t pred;
    asm volatile(
        "{\n\t"
        ".reg .pred p;\n\t"
        "elect.sync _|p, 0xFFFFFFFF;\n\t"
        "selp.b32 %0, 1, 0, p;\n\t"
        "}"
        : "=r"(pred));
    return pred;
}

__device__ __forceinline__ uint32_t smem_to_u32(const void* smem_ptr) {
    uint32_t addr;
    asm("{ .reg .u64 tmp; cvta.to.shared.u64 tmp, %1; cvt.u32.u64 %0, tmp; }"
        : "=r"(addr) : "l"(smem_ptr));
    return addr;
}

// SW64 swizzle: atom = 8 rows x 64 bytes
#define SMEM_SWIZZLE_64B(byte_offset) \
    ((byte_offset) ^ (((byte_offset) >> 3) & 0x30))

// SW64 smem descriptor: layout=4, version=1 (Blackwell), SBO=32 (512B per
// 8-row group), LBO=1 (16B inner stride). Rows are 64B wide.
static constexpr uint64_t SMEM_DESC_BASE_SW64 =
    (uint64_t(4)  << 61)
    | (uint64_t(1) << 46)
    | (uint64_t(32) << 32)
    | (uint64_t(1) << 16);

#define MAKE_SMEM_DESC64(base_addr) \
    (SMEM_DESC_BASE_SW64 | ((uint64_t)((base_addr) >> 4) & 0x3FFF))

#define TCGEN05_ALLOC(smem_result_addr, nCols) \
    asm volatile( \
        "tcgen05.alloc.cta_group::1.sync.aligned.shared::cta.b32 [%0], %1;" \
        :: "r"((uint32_t)(smem_result_addr)), "r"((uint32_t)(nCols)) \
        : "memory")

#define TCGEN05_DEALLOC(tmem_addr, nCols) \
    asm volatile( \
        "tcgen05.dealloc.cta_group::1.sync.aligned.b32 %0, %1;" \
        :: "r"(tmem_addr), "r"((uint32_t)(nCols)))

#define TCGEN05_RELINQUISH_ALLOC_PERMIT() \
    asm volatile("tcgen05.relinquish_alloc_permit.cta_group::1.sync.aligned;")

#define TCGEN05_COMMIT(mbar_smem_addr) \
    asm volatile( \
        "tcgen05.commit.cta_group::1.mbarrier::arrive::one.shared::cluster.b64 [%0];" \
        :: "r"((uint32_t)(mbar_smem_addr)) \
        : "memory")

#define TCGEN05_FENCE_AFTER() \
    asm volatile("tcgen05.fence::after_thread_sync;" ::: "memory")

#define TCGEN05_FENCE_BEFORE() \
    asm volatile("tcgen05.fence::before_thread_sync;" ::: "memory")

#define TCGEN05_WAIT_LD() \
    asm volatile("tcgen05.wait::ld.sync.aligned;" ::: "memory")

#define FENCE_PROXY_ASYNC_SHARED_CTA() \
    asm volatile("fence.proxy.async.shared::cta;" ::: "memory")

#define MBARRIER_INIT(mbar_smem_addr, count) \
    asm volatile( \
        "mbarrier.init.shared.b64 [%0], %1;" \
        :: "r"((uint32_t)(mbar_smem_addr)), "r"((uint32_t)(count)) \
        : "memory")

#define MBARRIER_WAIT_PARITY(mbar_smem_addr, phase_parity) do { \
    uint32_t _mbar = (uint32_t)(mbar_smem_addr); \
    uint32_t _parity = (uint32_t)(phase_parity); \
    uint32_t _done; \
    asm volatile( \
        "{\n\t" \
        ".reg .pred p;\n\t" \
        "mbarrier.try_wait.parity.acquire.cta.shared::cta.b64 p, [%1], %2;\n\t" \
        "selp.b32 %0, 1, 0, p;\n\t" \
        "}" \
        : "=r"(_done) : "r"(_mbar), "r"(_parity) : "memory"); \
    if (!_done) { \
        asm volatile( \
            "{\n\t" \
            ".reg .pred P1;\n\t" \
            "WAIT_LOOP_%=:\n\t" \
            "mbarrier.try_wait.parity.acquire.cta.shared::cta.b64 P1, [%0], %1, 0x989680;\n\t" \
            "@P1 bra.uni WAIT_DONE_%=;\n\t" \
            "bra.uni WAIT_LOOP_%=;\n\t" \
            "WAIT_DONE_%=:\n\t" \
            "}" \
            :: "r"(_mbar), "r"(_parity) : "memory"); \
    } \
} while(0)

#define TCGEN05_LD_32X32B_X16(r, tmem_addr) \
    asm volatile( \
        "tcgen05.ld.sync.aligned.32x32b.x16.b32 " \
        "{%0, %1, %2, %3, %4, %5, %6, %7, " \
        " %8, %9, %10, %11, %12, %13, %14, %15}, [%16];" \
        : "=r"((r)[0]),  "=r"((r)[1]),  "=r"((r)[2]),  "=r"((r)[3]), \
          "=r"((r)[4]),  "=r"((r)[5]),  "=r"((r)[6]),  "=r"((r)[7]), \
          "=r"((r)[8]),  "=r"((r)[9]),  "=r"((r)[10]), "=r"((r)[11]), \
          "=r"((r)[12]), "=r"((r)[13]), "=r"((r)[14]), "=r"((r)[15]) \
        : "r"(tmem_addr))

#if HAS_TC
// SS-mode cg1 bf16 MMA (kind::f16), fp32 accumulate in TMEM.
__device__ __forceinline__ void mma_f16_ss(uint32_t d_tmem, uint64_t a_desc,
                                           uint64_t b_desc, uint32_t idesc,
                                           uint32_t en) {
    asm volatile(
        "{\n\t"
        ".reg .pred p;\n\t"
        "setp.ne.u32 p, %5, 0;\n\t"
        "tcgen05.mma.cta_group::1.kind::f16 [%0], %1, %2, %3, {%4, %4, %4, %4}, p;\n\t"
        "}"
        :: "r"(d_tmem), "l"(a_desc), "l"(b_desc), "r"(idesc), "r"(0u), "r"(en)
        : "memory");
}

// 16-byte async copy, L2-only (.cg): streamed weights have no L1 reuse.
__device__ __forceinline__ void cp_async_16(uint32_t saddr, const void* gptr) {
    asm volatile(
        "{\n\t"
        ".reg .u64 g;\n\t"
        "cvta.to.global.u64 g, %1;\n\t"
        "cp.async.cg.shared.global [%0], [g], 16;\n\t"
        "}"
        :: "r"(saddr), "l"(gptr) : "memory");
}
#endif

// ============================================================================
// Shared memory layout. K-chunk = 32 (64B rows, SW64). Two pipeline stages.
// H-SPLIT: each CTA handles 64 of the 128 H columns -> B tile = 192 gate rows.
// Per stage: A_HI 8KB | A_LO 8KB | B_HI 12KB | B_LO 12KB = 40KB.
// Total 84KB per CTA -> 2 CTAs per SM (smem, TMEM 2x256 cols, regs).
// ============================================================================
static constexpr int SMEM_TMEMPTR   = 0;
static constexpr int SMEM_MBAR0     = 8;     // stage 0 "mma done"
static constexpr int SMEM_MBAR1     = 16;    // stage 1 "mma done"
static constexpr int SMEM_BIAS      = 32;    // 256 floats (r|z|xn_b|hn_b), 64 each
static constexpr int SMEM_STAGES    = 2048;
static constexpr int SMEM_STAGE_SZ  = 40960;
static constexpr int OFF_A_HI       = 0;      // 128 x 64B = 8 KB
static constexpr int OFF_A_LO       = 8192;   // 8 KB
static constexpr int OFF_B_HI       = 16384;  // 192 x 64B = 12 KB
static constexpr int OFF_B_LO       = 28672;  // 12 KB
static constexpr int SMEM_TOTAL     = SMEM_STAGES + 2 * SMEM_STAGE_SZ; // 83968

// idesc kind::f16 cg1: dtype=F32, atype=btype=BF16, N=64, M=128
static constexpr uint32_t IDESC =
    (1u << 4) | (1u << 7) | (1u << 10) | ((64u / 8) << 17) | ((128u / 16) << 24);

// ============================================================================
// Prep kernel: split fp32 weights into bf16 hi/lo pairs
// ============================================================================
__global__ void __launch_bounds__(256) gru_prep(const float* __restrict__ w_ih,
                                                const float* __restrict__ w_hh) {
    int i = blockIdx.x * 256 + threadIdx.x;
    if (i >= W_ELEMS) return;
    float v = w_ih[i];
    __nv_bfloat16 h = __float2bfloat16(v);
    g_wih_hi[i] = h;
    g_wih_lo[i] = __float2bfloat16(v - __bfloat162float(h));
    v = w_hh[i];
    h = __float2bfloat16(v);
    g_whh_hi[i] = h;
    g_whh_lo[i] = __float2bfloat16(v - __bfloat162float(h));
}

// ============================================================================
// Main fused GRU kernel. One CTA = (u, 128-row batch tile, 64-col H half).
// Pairs (hh=0 / hh=1) are adjacent in blockIdx.x so the duplicated A reads
// L2-hit. 256 threads, 2 CTAs/SM.
// TMEM D (256 cols): [0:64)=r_sum [64:128)=z_sum [128:192)=xn [192:256)=hn
// Pipeline: 8 chunks (2 sides x 4 K32-chunks), 2 smem stages.
// ============================================================================
__global__ void __launch_bounds__(256, 2) gru_main(
    const float* __restrict__ inputs,
    const float* __restrict__ hidden,
    const float* __restrict__ w_ih,
    const float* __restrict__ w_hh,
    const float* __restrict__ b_ih,
    const float* __restrict__ b_hh,
    float* __restrict__ out)
{
    extern __shared__ __align__(1024) char smem[];
    const int tid = threadIdx.x;
    const int u   = blockIdx.y;
    const int hh  = blockIdx.x & 1;          // H half: cols [hh*64, hh*64+64)
    const int b0  = (blockIdx.x >> 1) * 128; // batch-row tile

#if HAS_TC
    const uint32_t smem_base = smem_to_u32(smem);
    const int wid = tid >> 5;
    const int lid = tid & 31;

    if (wid == 0) {
        TCGEN05_ALLOC(smem_base + SMEM_TMEMPTR, 256);
        TCGEN05_RELINQUISH_ALLOC_PERMIT();
    }
    if (tid == 0) {
        MBARRIER_INIT(smem_base + SMEM_MBAR0, 1);
        MBARRIER_INIT(smem_base + SMEM_MBAR1, 1);
    }

    // bias: 4 x 64 floats for this H half: [r_sum | z_sum | xn_b | hn_b]
    float* bias = (float*)(smem + SMEM_BIAS);
    if (tid < 64) {
        const int c = tid;
        const int gr = 0 * H_DIM + hh * 64 + c;   // r row
        const int gz = 1 * H_DIM + hh * 64 + c;   // z row
        const int gn = 2 * H_DIM + hh * 64 + c;   // n row
        bias[c]       = b_ih[u * G3 + gr] + b_hh[u * G3 + gr];
        bias[64 + c]  = b_ih[u * G3 + gz] + b_hh[u * G3 + gz];
        bias[128 + c] = b_ih[u * G3 + gn];
        bias[192 + c] = b_hh[u * G3 + gn];
    }
    __syncthreads();

    uint32_t tmem_base;
    asm volatile("ld.shared.b32 %0, [%1];"
                 : "=r"(tmem_base) : "r"(smem_base + SMEM_TMEMPTR));

    // ---------------- pipelined mainloop: 8 chunks, 2 stages -----------------
    for (int ch = 0; ch < 8; ch++) {
        const int ph = ch >> 2;          // 0: x-side, 1: h-side
        const int cc = ch & 3;           // K32 chunk within side
        const int k0 = cc * 32;
        const int s  = ch & 1;
        const int stage = SMEM_STAGES + s * SMEM_STAGE_SZ;
        const uint32_t mbar = smem_base + (s ? SMEM_MBAR1 : SMEM_MBAR0);

        const float* asrc = ph ? hidden : inputs;
        const __nv_bfloat16* wh = ph ? g_whh_hi : g_wih_hi;
        const __nv_bfloat16* wl = ph ? g_whh_lo : g_wih_lo;

        // Backpressure: stage reused at ch-2; wait for its MMA commit.
        if (ch >= 2) MBARRIER_WAIT_PARITY(mbar, ((ch >> 1) + 1) & 1);

        // B tile via cp.async: 3 gates x 64 rows (this H half) x 64B, hi+lo
        #pragma unroll
        for (int i = 0; i < 3; i++) {
            const int q  = tid + i * 256;          // [0,768)
            const int lr = q >> 2;                 // local row 0..191
            const int gate = lr >> 6;              // 0=r 1=z 2=n
            const int g  = gate * H_DIM + hh * 64 + (lr & 63);
            const int ce = (q & 3) << 3;           // element col (x8 bf16)
            const size_t gi = (((size_t)u * G3) + g) * I_DIM + k0 + ce;
            const uint32_t off = SMEM_SWIZZLE_64B((uint32_t)(lr * 64 + (q & 3) * 16));
            cp_async_16(smem_base + stage + OFF_B_HI + off, wh + gi);
            cp_async_16(smem_base + stage + OFF_B_LO + off, wl + gi);
        }
        asm volatile("cp.async.commit_group;" ::: "memory");

        // A tile: 128 rows x 32 fp32 -> bf16 hi/lo split, SW64 swizzled
        #pragma unroll
        for (int i = 0; i < 4; i++) {
            const int q = tid + i * 256;           // [0,1024)
            const int row  = q >> 3;
            const int colf = (q & 7) << 2;
            const float4 v = *(const float4*)(asrc +
                (((size_t)(b0 + row)) * U_DIM + u) * I_DIM + k0 + colf);
            __nv_bfloat162 h0 = __float22bfloat162_rn(make_float2(v.x, v.y));
            __nv_bfloat162 h1 = __float22bfloat162_rn(make_float2(v.z, v.w));
            float2 r0 = make_float2(v.x - __bfloat162float(h0.x),
                                    v.y - __bfloat162float(h0.y));
            float2 r1 = make_float2(v.z - __bfloat162float(h1.x),
                                    v.w - __bfloat162float(h1.y));
            __nv_bfloat162 l0 = __float22bfloat162_rn(r0);
            __nv_bfloat162 l1 = __float22bfloat162_rn(r1);
            const uint32_t off = SMEM_SWIZZLE_64B((uint32_t)(row * 64 + colf * 2));
            *(uint2*)(smem + stage + OFF_A_HI + off) =
                make_uint2(*(uint32_t*)&h0, *(uint32_t*)&h1);
            *(uint2*)(smem + stage + OFF_A_LO + off) =
                make_uint2(*(uint32_t*)&l0, *(uint32_t*)&l1);
        }

        asm volatile("cp.async.wait_group 0;" ::: "memory");
        FENCE_PROXY_ASYNC_SHARED_CTA();
        __syncthreads();

        // MMA issue: 3 split terms x 2 K16 steps x 3 gate tiles (N=64) = 18
        if (wid == 0) {
            if (elect_one_pred()) {
                const uint32_t sb = smem_base + stage;
                const uint64_t adh = MAKE_SMEM_DESC64(sb + OFF_A_HI);
                const uint64_t adl = MAKE_SMEM_DESC64(sb + OFF_A_LO);
                const uint64_t bdh = MAKE_SMEM_DESC64(sb + OFF_B_HI);
                const uint64_t bdl = MAKE_SMEM_DESC64(sb + OFF_B_LO);
                #pragma unroll
                for (int term = 0; term < 3; term++) {
                    const uint64_t ad = (term == 2) ? adl : adh;
                    const uint64_t bd = (term == 1) ? bdl : bdh;
                    #pragma unroll
                    for (int ks = 0; ks < 2; ks++) {
                        #pragma unroll
                        for (int nt = 0; nt < 3; nt++) {
                            // gate tiles: nt 0=r, 1=z, 2=n (xn on ph0, hn on ph1)
                            const uint32_t dcol =
                                (ph == 1 && nt == 2) ? 192u : (uint32_t)(nt * 64);
                            const uint32_t first =
                                (cc == 0 && term == 0 && ks == 0) ? 1u : 0u;
                            uint32_t en;
                            if (ph == 0)
                                en = first ? 0u : 1u;           // r,z,xn first touch
                            else
                                en = (nt < 2) ? 1u : (first ? 0u : 1u); // hn first
                            mma_f16_ss(tmem_base + dcol,
                                       ad + ks * 2,
                                       bd + nt * 256 + ks * 2,
                                       IDESC, en);
                        }
                    }
                }
                TCGEN05_COMMIT(mbar);
            }
        }
    }

    // Final commits: each stage committed 4 times -> parity 1.
    MBARRIER_WAIT_PARITY(smem_base + SMEM_MBAR0, 1);
    MBARRIER_WAIT_PARITY(smem_base + SMEM_MBAR1, 1);
    TCGEN05_FENCE_AFTER();

    // ---------------- epilogue: TMEM -> GRU elementwise -> GMEM --------------
    // Warps 0-3 local cols [0,32), warps 4-7 [32,64); TMEM subpart = wid & 3.
    const int row = (wid & 3) * 32 + lid;
    const int c0  = (wid >> 2) * 32;
    const float* hrow = hidden + (((size_t)(b0 + row)) * U_DIM + u) * H_DIM + hh * 64;
    float*       orow = out    + (((size_t)(b0 + row)) * U_DIM + u) * H_DIM + hh * 64;

    for (int cb = c0; cb < c0 + 32; cb += 16) {
        uint32_t rr[16], zz[16], xn[16], hn[16];
        TCGEN05_LD_32X32B_X16(rr, tmem_base + cb);
        TCGEN05_LD_32X32B_X16(zz, tmem_base + 64 + cb);
        TCGEN05_LD_32X32B_X16(xn, tmem_base + 128 + cb);
        TCGEN05_LD_32X32B_X16(hn, tmem_base + 192 + cb);
        TCGEN05_WAIT_LD();

        float4 hv[4];
        const float4* hp = (const float4*)(hrow + cb);
        hv[0] = hp[0]; hv[1] = hp[1]; hv[2] = hp[2]; hv[3] = hp[3];
        const float* hvf = (const float*)hv;

        float res[16];
        #pragma unroll
        for (int j = 0; j < 16; j++) {
            const int c = cb + j;                 // local col in [0,64)
            const float vr = __uint_as_float(rr[j]) + bias[c];
            const float vz = __uint_as_float(zz[j]) + bias[64 + c];
            const float r  = 1.f / (1.f + __expf(-vr));
            const float z  = 1.f / (1.f + __expf(-vz));
            const float vn = __uint_as_float(xn[j]) + bias[128 + c]
                           + r * (__uint_as_float(hn[j]) + bias[192 + c]);
            const float n  = tanhf(vn);
            res[j] = (1.f - z) * n + z * hvf[j];
        }
        TCGEN05_FENCE_BEFORE();
        float4* op = (float4*)(orow + cb);
        op[0] = ((float4*)res)[0];
        op[1] = ((float4*)res)[1];
        op[2] = ((float4*)res)[2];
        op[3] = ((float4*)res)[3];
    }

    __syncthreads();
    if (wid == 0) {
        TCGEN05_DEALLOC(tmem_base, 256);
    }

#else  // ---------------- fallback: plain fp32 FFMA (non-sm_103a targets) ----
    // Correct but slow; only executes if the runtime ever JITs the plain
    // compute_103 PTX instead of using the sm_103a cubin.
    float* xs = (float*)smem;              // 128 x 128
    float* hs = xs + 128 * 128;            // 128 x 128
    for (int q = tid; q < 128 * 128; q += 256) {
        const int row = q >> 7, col = q & 127;
        const size_t base = (((size_t)(b0 + row)) * U_DIM + u) * I_DIM + col;
        xs[q] = inputs[base];
        hs[q] = hidden[base];
    }
    __syncthreads();

    if (tid < 128) {
        const float* xr_ = xs + tid * 128;
        const float* hr_ = hs + tid * 128;
        float* orow = out + (((size_t)(b0 + tid)) * U_DIM + u) * H_DIM;

        for (int cl = 0; cl < 64; cl++) {
            const int c = hh * 64 + cl;
            float axr = b_ih[u * G3 + c],       ahr = b_hh[u * G3 + c];
            float axz = b_ih[u * G3 + 128 + c], ahz = b_hh[u * G3 + 128 + c];
            float axn = b_ih[u * G3 + 256 + c], ahn = b_hh[u * G3 + 256 + c];
            const float* wir = w_ih + (((size_t)u * G3) + c) * I_DIM;
            const float* whr = w_hh + (((size_t)u * G3) + c) * I_DIM;
            for (int k = 0; k < I_DIM; k++) {
                const float xv = xr_[k], hv = hr_[k];
                axr += xv * wir[k];
                axz += xv * wir[128 * I_DIM + k];
                axn += xv * wir[256 * I_DIM + k];
                ahr += hv * whr[k];
                ahz += hv * whr[128 * I_DIM + k];
                ahn += hv * whr[256 * I_DIM + k];
            }
            const float r = 1.f / (1.f + expf(-(axr + ahr)));
            const float z = 1.f / (1.f + expf(-(axz + ahz)));
            const float n = tanhf(axn + r * ahn);
            orow[c] = (1.f - z) * n + z * hr_[c];
        }
    }
#endif
}

// ============================================================================
// kernel_launch — graph-capturable, allocation-free
// ============================================================================
extern "C" void kernel_launch(void* const* d_in, const int* in_sizes, int n_in,
                              void* d_out, int out_size) {
    const float* inputs = (const float*)d_in[0];
    const float* hidden = (const float*)d_in[1];
    const float* w_ih   = (const float*)d_in[2];
    const float* w_hh   = (const float*)d_in[3];
    const float* b_ih   = (const float*)d_in[4];
    const float* b_hh   = (const float*)d_in[5];
    float* out = (float*)d_out;

    const int B = in_sizes[0] / (U_DIM * I_DIM);   // 8192

    gru_prep<<<(W_ELEMS + 255) / 256, 256>>>(w_ih, w_hh);

    cudaFuncSetAttribute(gru_main,
                         cudaFuncAttributeMaxDynamicSharedMemorySize, SMEM_TOTAL);
    // blockIdx.x = (batch-tile << 1) | H-half  -> pairs adjacent for L2 reuse
    gru_main<<<dim3((B / 128) * 2, U_DIM), 256, SMEM_TOTAL>>>(
        inputs, hidden, w_ih, w_hh, b_ih, b_hh, out);
}

// round 15
// speedup vs baseline: 1.4225x; 1.0662x over previous
#include <cuda_runtime.h>
#include <cuda_bf16.h>
#include <cstdint>

// ============================================================================
// Arch gating: tcgen05/TMEM are sm_103a ("arch-specific") features. The
// harness also compiles a plain compute_103 stage, which must not see any
// tcgen05 PTX. HAS_TC selects the real tensor-core path only on the
// arch-specific device pass; all other passes get a correct FFMA fallback.
// ============================================================================
#if defined(__CUDA_ARCH__) && \
    (defined(__CUDA_ARCH_FEAT_SM103_ALL) || defined(__CUDA_ARCH_FEAT_SM100_ALL) || \
     defined(__CUDA_ARCH_SPECIFIC__) || defined(__CUDA_ARCH_FAMILY_SPECIFIC__))
#define HAS_TC 1
#else
#define HAS_TC 0
#endif

// ============================================================================
// Problem constants: B=8192 (derived at launch), U=16, I=H=128, 3H=384 gates
// ============================================================================
#define U_DIM 16
#define I_DIM 128
#define H_DIM 128
#define G3    384
#define W_ELEMS (U_DIM * G3 * I_DIM)   // 786432 per weight matrix

// Pre-split weights (fp32 -> bf16 hi + bf16 lo), filled by prep kernel.
__device__ __nv_bfloat16 g_wih_hi[W_ELEMS];
__device__ __nv_bfloat16 g_wih_lo[W_ELEMS];
__device__ __nv_bfloat16 g_whh_hi[W_ELEMS];
__device__ __nv_bfloat16 g_whh_lo[W_ELEMS];

// ============================================================================
// PTX helpers
// ============================================================================
__device__ __forceinline__ uint32_t elect_one_pred() {
    uint32_t pred;
    asm volatile(
        "{\n\t"
        ".reg .pred p;\n\t"
        "elect.sync _|p, 0xFFFFFFFF;\n\t"
        "selp.b32 %0, 1, 0, p;\n\t"
        "}"
        : "=r"(pred));
    return pred;
}

__device__ __forceinline__ uint32_t smem_to_u32(const void* smem_ptr) {
    uint32_t addr;
    asm("{ .reg .u64 tmp; cvta.to.shared.u64 tmp, %1; cvt.u32.u64 %0, tmp; }"
        : "=r"(addr) : "l"(smem_ptr));
    return addr;
}

// Single-instruction MUFU tanh (sm_75+). Max abs err ~1e-5 — far inside the
// 1e-3 rel-err budget. sigmoid(x) == 0.5*tanh(0.5x)+0.5 exactly.
__device__ __forceinline__ float fast_tanh(float x) {
    float y;
    asm("tanh.approx.f32 %0, %1;" : "=f"(y) : "f"(x));
    return y;
}

// SW64 swizzle: atom = 8 rows x 64 bytes
#define SMEM_SWIZZLE_64B(byte_offset) \
    ((byte_offset) ^ (((byte_offset) >> 3) & 0x30))

// SW64 smem descriptor: layout=4, version=1 (Blackwell), SBO=32 (512B per
// 8-row group), LBO=1 (16B inner stride). Rows are 64B wide.
static constexpr uint64_t SMEM_DESC_BASE_SW64 =
    (uint64_t(4)  << 61)
    | (uint64_t(1) << 46)
    | (uint64_t(32) << 32)
    | (uint64_t(1) << 16);

#define MAKE_SMEM_DESC64(base_addr) \
    (SMEM_DESC_BASE_SW64 | ((uint64_t)((base_addr) >> 4) & 0x3FFF))

#define TCGEN05_ALLOC(smem_result_addr, nCols) \
    asm volatile( \
        "tcgen05.alloc.cta_group::1.sync.aligned.shared::cta.b32 [%0], %1;" \
        :: "r"((uint32_t)(smem_result_addr)), "r"((uint32_t)(nCols)) \
        : "memory")

#define TCGEN05_DEALLOC(tmem_addr, nCols) \
    asm volatile( \
        "tcgen05.dealloc.cta_group::1.sync.aligned.b32 %0, %1;" \
        :: "r"(tmem_addr), "r"((uint32_t)(nCols)))

#define TCGEN05_RELINQUISH_ALLOC_PERMIT() \
    asm volatile("tcgen05.relinquish_alloc_permit.cta_group::1.sync.aligned;")

#define TCGEN05_COMMIT(mbar_smem_addr) \
    asm volatile( \
        "tcgen05.commit.cta_group::1.mbarrier::arrive::one.shared::cluster.b64 [%0];" \
        :: "r"((uint32_t)(mbar_smem_addr)) \
        : "memory")

#define TCGEN05_FENCE_AFTER() \
    asm volatile("tcgen05.fence::after_thread_sync;" ::: "memory")

#define TCGEN05_FENCE_BEFORE() \
    asm volatile("tcgen05.fence::before_thread_sync;" ::: "memory")

#define TCGEN05_WAIT_LD() \
    asm volatile("tcgen05.wait::ld.sync.aligned;" ::: "memory")

#define FENCE_PROXY_ASYNC_SHARED_CTA() \
    asm volatile("fence.proxy.async.shared::cta;" ::: "memory")

#define MBARRIER_INIT(mbar_smem_addr, count) \
    asm volatile( \
        "mbarrier.init.shared.b64 [%0], %1;" \
        :: "r"((uint32_t)(mbar_smem_addr)), "r"((uint32_t)(count)) \
        : "memory")

#define MBARRIER_ARRIVE(mbar_smem_addr) \
    asm volatile( \
        "mbarrier.arrive.release.cta.shared::cta.b64 _, [%0];" \
        :: "r"((uint32_t)(mbar_smem_addr)) \
        : "memory")

#define MBARRIER_WAIT_PARITY(mbar_smem_addr, phase_parity) do { \
    uint32_t _mbar = (uint32_t)(mbar_smem_addr); \
    uint32_t _parity = (uint32_t)(phase_parity); \
    uint32_t _done; \
    asm volatile( \
        "{\n\t" \
        ".reg .pred p;\n\t" \
        "mbarrier.try_wait.parity.acquire.cta.shared::cta.b64 p, [%1], %2;\n\t" \
        "selp.b32 %0, 1, 0, p;\n\t" \
        "}" \
        : "=r"(_done) : "r"(_mbar), "r"(_parity) : "memory"); \
    if (!_done) { \
        asm volatile( \
            "{\n\t" \
            ".reg .pred P1;\n\t" \
            "WAIT_LOOP_%=:\n\t" \
            "mbarrier.try_wait.parity.acquire.cta.shared::cta.b64 P1, [%0], %1, 0x989680;\n\t" \
            "@P1 bra.uni WAIT_DONE_%=;\n\t" \
            "bra.uni WAIT_LOOP_%=;\n\t" \
            "WAIT_DONE_%=:\n\t" \
            "}" \
            :: "r"(_mbar), "r"(_parity) : "memory"); \
    } \
} while(0)

#define TCGEN05_LD_32X32B_X16(r, tmem_addr) \
    asm volatile( \
        "tcgen05.ld.sync.aligned.32x32b.x16.b32 " \
        "{%0, %1, %2, %3, %4, %5, %6, %7, " \
        " %8, %9, %10, %11, %12, %13, %14, %15}, [%16];" \
        : "=r"((r)[0]),  "=r"((r)[1]),  "=r"((r)[2]),  "=r"((r)[3]), \
          "=r"((r)[4]),  "=r"((r)[5]),  "=r"((r)[6]),  "=r"((r)[7]), \
          "=r"((r)[8]),  "=r"((r)[9]),  "=r"((r)[10]), "=r"((r)[11]), \
          "=r"((r)[12]), "=r"((r)[13]), "=r"((r)[14]), "=r"((r)[15]) \
        : "r"(tmem_addr))

#if HAS_TC
// SS-mode cg1 bf16 MMA (kind::f16), fp32 accumulate in TMEM.
__device__ __forceinline__ void mma_f16_ss(uint32_t d_tmem, uint64_t a_desc,
                                           uint64_t b_desc, uint32_t idesc,
                                           uint32_t en) {
    asm volatile(
        "{\n\t"
        ".reg .pred p;\n\t"
        "setp.ne.u32 p, %5, 0;\n\t"
        "tcgen05.mma.cta_group::1.kind::f16 [%0], %1, %2, %3, {%4, %4, %4, %4}, p;\n\t"
        "}"
        :: "r"(d_tmem), "l"(a_desc), "l"(b_desc), "r"(idesc), "r"(0u), "r"(en)
        : "memory");
}

// 16-byte async copy, L2-only (.cg): streamed weights have no L1 reuse.
__device__ __forceinline__ void cp_async_16(uint32_t saddr, const void* gptr) {
    asm volatile(
        "{\n\t"
        ".reg .u64 g;\n\t"
        "cvta.to.global.u64 g, %1;\n\t"
        "cp.async.cg.shared.global [%0], [g], 16;\n\t"
        "}"
        :: "r"(saddr), "l"(gptr) : "memory");
}
#endif

// ============================================================================
// Shared memory layout. K-chunk = 32 (64B rows, SW64). Two pipeline stages.
// H-SPLIT: each CTA handles 64 of the 128 H columns -> B tile = 192 gate rows.
// Per stage: A_HI 8KB | A_LO 8KB | B_HI 12KB | B_LO 12KB = 40KB.
// Total 84KB per CTA -> 2 CTAs per SM (smem, TMEM 2x256 cols, regs).
// ============================================================================
static constexpr int SMEM_TMEMPTR   = 0;
static constexpr int SMEM_DONE0     = 8;     // stage 0 "mma done" (commit)
static constexpr int SMEM_DONE1     = 16;    // stage 1 "mma done"
static constexpr int SMEM_FULL0     = 24;    // stage 0 "tiles ready" (256 arrivals)
static constexpr int SMEM_FULL1     = 32;    // stage 1 "tiles ready"
static constexpr int SMEM_BIAS      = 64;    // 256 floats (r|z|xn_b|hn_b), 64 each
static constexpr int SMEM_STAGES    = 2048;
static constexpr int SMEM_STAGE_SZ  = 40960;
static constexpr int OFF_A_HI       = 0;      // 128 x 64B = 8 KB
static constexpr int OFF_A_LO       = 8192;   // 8 KB
static constexpr int OFF_B_HI       = 16384;  // 192 x 64B = 12 KB
static constexpr int OFF_B_LO       = 28672;  // 12 KB
static constexpr int SMEM_TOTAL     = SMEM_STAGES + 2 * SMEM_STAGE_SZ; // 83968

// idesc kind::f16 cg1: dtype=F32, atype=btype=BF16, N=64, M=128
static constexpr uint32_t IDESC =
    (1u << 4) | (1u << 7) | (1u << 10) | ((64u / 8) << 17) | ((128u / 16) << 24);

// ============================================================================
// Prep kernel: split fp32 weights into bf16 hi/lo pairs
// ============================================================================
__global__ void __launch_bounds__(256) gru_prep(const float* __restrict__ w_ih,
                                                const float* __restrict__ w_hh) {
    int i = blockIdx.x * 256 + threadIdx.x;
    if (i >= W_ELEMS) return;
    float v = w_ih[i];
    __nv_bfloat16 h = __float2bfloat16(v);
    g_wih_hi[i] = h;
    g_wih_lo[i] = __float2bfloat16(v - __bfloat162float(h));
    v = w_hh[i];
    h = __float2bfloat16(v);
    g_whh_hi[i] = h;
    g_whh_lo[i] = __float2bfloat16(v - __bfloat162float(h));
}

// ============================================================================
// Main fused GRU kernel. One CTA = (u, 128-row batch tile, 64-col H half).
// Pairs (hh=0 / hh=1) are adjacent in blockIdx.x so the duplicated A reads
// L2-hit. 256 threads, 2 CTAs/SM.
// TMEM D (256 cols): [0:64)=r_sum [64:128)=z_sum [128:192)=xn [192:256)=hn
// Pipeline: 8 chunks (2 sides x 4 K32-chunks), 2 smem stages. No per-chunk
// __syncthreads: producers arrive on a per-stage FULL mbarrier (count=256),
// the single MMA thread acquire-waits FULL and issues; producers only block
// on the stage's DONE commit two chunks back.
// ============================================================================
__global__ void __launch_bounds__(256, 2) gru_main(
    const float* __restrict__ inputs,
    const float* __restrict__ hidden,
    const float* __restrict__ w_ih,
    const float* __restrict__ w_hh,
    const float* __restrict__ b_ih,
    const float* __restrict__ b_hh,
    float* __restrict__ out)
{
    extern __shared__ __align__(1024) char smem[];
    const int tid = threadIdx.x;
    const int u   = blockIdx.y;
    const int hh  = blockIdx.x & 1;          // H half: cols [hh*64, hh*64+64)
    const int b0  = (blockIdx.x >> 1) * 128; // batch-row tile

#if HAS_TC
    const uint32_t smem_base = smem_to_u32(smem);
    const int wid = tid >> 5;
    const int lid = tid & 31;

    if (wid == 0) {
        TCGEN05_ALLOC(smem_base + SMEM_TMEMPTR, 256);
        TCGEN05_RELINQUISH_ALLOC_PERMIT();
    }
    if (tid == 0) {
        MBARRIER_INIT(smem_base + SMEM_DONE0, 1);
        MBARRIER_INIT(smem_base + SMEM_DONE1, 1);
        MBARRIER_INIT(smem_base + SMEM_FULL0, 256);
        MBARRIER_INIT(smem_base + SMEM_FULL1, 256);
    }

    // bias: 4 x 64 floats for this H half: [r_sum | z_sum | xn_b | hn_b]
    float* bias = (float*)(smem + SMEM_BIAS);
    if (tid < 64) {
        const int c = tid;
        const int gr = 0 * H_DIM + hh * 64 + c;   // r row
        const int gz = 1 * H_DIM + hh * 64 + c;   // z row
        const int gn = 2 * H_DIM + hh * 64 + c;   // n row
        bias[c]       = b_ih[u * G3 + gr] + b_hh[u * G3 + gr];
        bias[64 + c]  = b_ih[u * G3 + gz] + b_hh[u * G3 + gz];
        bias[128 + c] = b_ih[u * G3 + gn];
        bias[192 + c] = b_hh[u * G3 + gn];
    }
    __syncthreads();   // mbarrier init + bias visible to all threads

    uint32_t tmem_base;
    asm volatile("ld.shared.b32 %0, [%1];"
                 : "=r"(tmem_base) : "r"(smem_base + SMEM_TMEMPTR));

    // ---------------- pipelined mainloop: 8 chunks, 2 stages -----------------
    for (int ch = 0; ch < 8; ch++) {
        const int ph = ch >> 2;          // 0: x-side, 1: h-side
        const int cc = ch & 3;           // K32 chunk within side
        const int k0 = cc * 32;
        const int s  = ch & 1;
        const int stage = SMEM_STAGES + s * SMEM_STAGE_SZ;
        const uint32_t done_mbar = smem_base + (s ? SMEM_DONE1 : SMEM_DONE0);
        const uint32_t full_mbar = smem_base + (s ? SMEM_FULL1 : SMEM_FULL0);

        const float* asrc = ph ? hidden : inputs;
        const __nv_bfloat16* wh = ph ? g_whh_hi : g_wih_hi;
        const __nv_bfloat16* wl = ph ? g_whh_lo : g_wih_lo;

        // Backpressure: stage reused at ch-2; wait for its MMA commit.
        if (ch >= 2) MBARRIER_WAIT_PARITY(done_mbar, ((ch >> 1) + 1) & 1);

        // B tile via cp.async: 3 gates x 64 rows (this H half) x 64B, hi+lo
        #pragma unroll
        for (int i = 0; i < 3; i++) {
            const int q  = tid + i * 256;          // [0,768)
            const int lr = q >> 2;                 // local row 0..191
            const int gate = lr >> 6;              // 0=r 1=z 2=n
            const int g  = gate * H_DIM + hh * 64 + (lr & 63);
            const int ce = (q & 3) << 3;           // element col (x8 bf16)
            const size_t gi = (((size_t)u * G3) + g) * I_DIM + k0 + ce;
            const uint32_t off = SMEM_SWIZZLE_64B((uint32_t)(lr * 64 + (q & 3) * 16));
            cp_async_16(smem_base + stage + OFF_B_HI + off, wh + gi);
            cp_async_16(smem_base + stage + OFF_B_LO + off, wl + gi);
        }
        asm volatile("cp.async.commit_group;" ::: "memory");

        // A tile: 128 rows x 32 fp32 -> bf16 hi/lo split, SW64 swizzled
        #pragma unroll
        for (int i = 0; i < 4; i++) {
            const int q = tid + i * 256;           // [0,1024)
            const int row  = q >> 3;
            const int colf = (q & 7) << 2;
            const float4 v = *(const float4*)(asrc +
                (((size_t)(b0 + row)) * U_DIM + u) * I_DIM + k0 + colf);
            __nv_bfloat162 h0 = __float22bfloat162_rn(make_float2(v.x, v.y));
            __nv_bfloat162 h1 = __float22bfloat162_rn(make_float2(v.z, v.w));
            float2 r0 = make_float2(v.x - __bfloat162float(h0.x),
                                    v.y - __bfloat162float(h0.y));
            float2 r1 = make_float2(v.z - __bfloat162float(h1.x),
                                    v.w - __bfloat162float(h1.y));
            __nv_bfloat162 l0 = __float22bfloat162_rn(r0);
            __nv_bfloat162 l1 = __float22bfloat162_rn(r1);
            const uint32_t off = SMEM_SWIZZLE_64B((uint32_t)(row * 64 + colf * 2));
            *(uint2*)(smem + stage + OFF_A_HI + off) =
                make_uint2(*(uint32_t*)&h0, *(uint32_t*)&h1);
            *(uint2*)(smem + stage + OFF_A_LO + off) =
                make_uint2(*(uint32_t*)&l0, *(uint32_t*)&l1);
        }

        asm volatile("cp.async.wait_group 0;" ::: "memory");
        FENCE_PROXY_ASYNC_SHARED_CTA();
        MBARRIER_ARRIVE(full_mbar);

        // Single MMA agent: wait all 256 producer arrivals, then issue.
        // 3 split terms x 2 K16 steps x 3 gate tiles (N=64) = 18 dispatches.
        if (wid == 0) {
            if (elect_one_pred()) {
                MBARRIER_WAIT_PARITY(full_mbar, (ch >> 1) & 1);
                const uint32_t sb = smem_base + stage;
                const uint64_t adh = MAKE_SMEM_DESC64(sb + OFF_A_HI);
                const uint64_t adl = MAKE_SMEM_DESC64(sb + OFF_A_LO);
                const uint64_t bdh = MAKE_SMEM_DESC64(sb + OFF_B_HI);
                const uint64_t bdl = MAKE_SMEM_DESC64(sb + OFF_B_LO);
                #pragma unroll
                for (int term = 0; term < 3; term++) {
                    const uint64_t ad = (term == 2) ? adl : adh;
                    const uint64_t bd = (term == 1) ? bdl : bdh;
                    #pragma unroll
                    for (int ks = 0; ks < 2; ks++) {
                        #pragma unroll
                        for (int nt = 0; nt < 3; nt++) {
                            // gate tiles: nt 0=r, 1=z, 2=n (xn on ph0, hn on ph1)
                            const uint32_t dcol =
                                (ph == 1 && nt == 2) ? 192u : (uint32_t)(nt * 64);
                            const uint32_t first =
                                (cc == 0 && term == 0 && ks == 0) ? 1u : 0u;
                            uint32_t en;
                            if (ph == 0)
                                en = first ? 0u : 1u;           // r,z,xn first touch
                            else
                                en = (nt < 2) ? 1u : (first ? 0u : 1u); // hn first
                            mma_f16_ss(tmem_base + dcol,
                                       ad + ks * 2,
                                       bd + nt * 256 + ks * 2,
                                       IDESC, en);
                        }
                    }
                }
                TCGEN05_COMMIT(done_mbar);
            }
        }
    }

    // Final commits: each stage committed 4 times -> parity 1.
    MBARRIER_WAIT_PARITY(smem_base + SMEM_DONE0, 1);
    MBARRIER_WAIT_PARITY(smem_base + SMEM_DONE1, 1);
    TCGEN05_FENCE_AFTER();

    // ---------------- epilogue: TMEM -> GRU elementwise -> GMEM --------------
    // Warps 0-3 local cols [0,32), warps 4-7 [32,64); TMEM subpart = wid & 3.
    const int row = (wid & 3) * 32 + lid;
    const int c0  = (wid >> 2) * 32;
    const float* hrow = hidden + (((size_t)(b0 + row)) * U_DIM + u) * H_DIM + hh * 64;
    float*       orow = out    + (((size_t)(b0 + row)) * U_DIM + u) * H_DIM + hh * 64;

    for (int cb = c0; cb < c0 + 32; cb += 16) {
        uint32_t rr[16], zz[16], xn[16], hn[16];
        TCGEN05_LD_32X32B_X16(rr, tmem_base + cb);
        TCGEN05_LD_32X32B_X16(zz, tmem_base + 64 + cb);
        TCGEN05_LD_32X32B_X16(xn, tmem_base + 128 + cb);
        TCGEN05_LD_32X32B_X16(hn, tmem_base + 192 + cb);
        TCGEN05_WAIT_LD();

        float4 hv[4];
        const float4* hp = (const float4*)(hrow + cb);
        hv[0] = hp[0]; hv[1] = hp[1]; hv[2] = hp[2]; hv[3] = hp[3];
        const float* hvf = (const float*)hv;

        float res[16];
        #pragma unroll
        for (int j = 0; j < 16; j++) {
            const int c = cb + j;                 // local col in [0,64)
            const float vr = __uint_as_float(rr[j]) + bias[c];
            const float vz = __uint_as_float(zz[j]) + bias[64 + c];
            // sigmoid(x) = 0.5*tanh(0.5x)+0.5 (exact identity, MUFU.TANH)
            const float r  = fmaf(fast_tanh(0.5f * vr), 0.5f, 0.5f);
            const float z  = fmaf(fast_tanh(0.5f * vz), 0.5f, 0.5f);
            const float vn = __uint_as_float(xn[j]) + bias[128 + c]
                           + r * (__uint_as_float(hn[j]) + bias[192 + c]);
            const float n  = fast_tanh(vn);
            res[j] = n + z * (hvf[j] - n);        // (1-z)*n + z*h
        }
        TCGEN05_FENCE_BEFORE();
        float4* op = (float4*)(orow + cb);
        op[0] = ((float4*)res)[0];
        op[1] = ((float4*)res)[1];
        op[2] = ((float4*)res)[2];
        op[3] = ((float4*)res)[3];
    }

    __syncthreads();
    if (wid == 0) {
        TCGEN05_DEALLOC(tmem_base, 256);
    }

#else  // ---------------- fallback: plain fp32 FFMA (non-sm_103a targets) ----
    // Correct but slow; only executes if the runtime ever JITs the plain
    // compute_103 PTX instead of using the sm_103a cubin.
    float* xs = (float*)smem;              // 128 x 128
    float* hs = xs + 128 * 128;            // 128 x 128
    for (int q = tid; q < 128 * 128; q += 256) {
        const int row = q >> 7, col = q & 127;
        const size_t base = (((size_t)(b0 + row)) * U_DIM + u) * I_DIM + col;
        xs[q] = inputs[base];
        hs[q] = hidden[base];
    }
    __syncthreads();

    if (tid < 128) {
        const float* xr_ = xs + tid * 128;
        const float* hr_ = hs + tid * 128;
        float* orow = out + (((size_t)(b0 + tid)) * U_DIM + u) * H_DIM;

        for (int cl = 0; cl < 64; cl++) {
            const int c = hh * 64 + cl;
            float axr = b_ih[u * G3 + c],       ahr = b_hh[u * G3 + c];
            float axz = b_ih[u * G3 + 128 + c], ahz = b_hh[u * G3 + 128 + c];
            float axn = b_ih[u * G3 + 256 + c], ahn = b_hh[u * G3 + 256 + c];
            const float* wir = w_ih + (((size_t)u * G3) + c) * I_DIM;
            const float* whr = w_hh + (((size_t)u * G3) + c) * I_DIM;
            for (int k = 0; k < I_DIM; k++) {
                const float xv = xr_[k], hv = hr_[k];
                axr += xv * wir[k];
                axz += xv * wir[128 * I_DIM + k];
                axn += xv * wir[256 * I_DIM + k];
                ahr += hv * whr[k];
                ahz += hv * whr[128 * I_DIM + k];
                ahn += hv * whr[256 * I_DIM + k];
            }
            const float r = 1.f / (1.f + expf(-(axr + ahr)));
            const float z = 1.f / (1.f + expf(-(axz + ahz)));
            const float n = tanhf(axn + r * ahn);
            orow[c] = (1.f - z) * n + z * hr_[c];
        }
    }
#endif
}

// ============================================================================
// kernel_launch — graph-capturable, allocation-free
// ============================================================================
extern "C" void kernel_launch(void* const* d_in, const int* in_sizes, int n_in,
                              void* d_out, int out_size) {
    const float* inputs = (const float*)d_in[0];
    const float* hidden = (const float*)d_in[1];
    const float* w_ih   = (const float*)d_in[2];
    const float* w_hh   = (const float*)d_in[3];
    const float* b_ih   = (const float*)d_in[4];
    const float* b_hh   = (const float*)d_in[5];
    float* out = (float*)d_out;

    const int B = in_sizes[0] / (U_DIM * I_DIM);   // 8192

    gru_prep<<<(W_ELEMS + 255) / 256, 256>>>(w_ih, w_hh);

    cudaFuncSetAttribute(gru_main,
                         cudaFuncAttributeMaxDynamicSharedMemorySize, SMEM_TOTAL);
    // blockIdx.x = (batch-tile << 1) | H-half  -> pairs adjacent for L2 reuse
    gru_main<<<dim3((B / 128) * 2, U_DIM), 256, SMEM_TOTAL>>>(
        inputs, hidden, w_ih, w_hh, b_ih, b_hh, out);
}

// round 16
// speedup vs baseline: 1.5244x; 1.0717x over previous
#include <cuda_runtime.h>
#include <cuda_bf16.h>
#include <cstdint>

// ============================================================================
// Arch gating: tcgen05/TMEM are sm_103a ("arch-specific") features. The
// harness also compiles a plain compute_103 stage, which must not see any
// tcgen05 PTX. HAS_TC selects the real tensor-core path only on the
// arch-specific device pass; all other passes get a correct FFMA fallback.
// ============================================================================
#if defined(__CUDA_ARCH__) && \
    (defined(__CUDA_ARCH_FEAT_SM103_ALL) || defined(__CUDA_ARCH_FEAT_SM100_ALL) || \
     defined(__CUDA_ARCH_SPECIFIC__) || defined(__CUDA_ARCH_FAMILY_SPECIFIC__))
#define HAS_TC 1
#else
#define HAS_TC 0
#endif

// ============================================================================
// Problem constants: B=8192 (derived at launch), U=16, I=H=128, 3H=384 gates
// ============================================================================
#define U_DIM 16
#define I_DIM 128
#define H_DIM 128
#define G3    384
#define W_ELEMS (U_DIM * G3 * I_DIM)   // 786432 per weight matrix

// Pre-split weights (fp32 -> bf16 hi + bf16 lo), filled by prep kernel.
__device__ __nv_bfloat16 g_wih_hi[W_ELEMS];
__device__ __nv_bfloat16 g_wih_lo[W_ELEMS];
__device__ __nv_bfloat16 g_whh_hi[W_ELEMS];
__device__ __nv_bfloat16 g_whh_lo[W_ELEMS];

// ============================================================================
// PTX helpers
// ============================================================================
__device__ __forceinline__ uint32_t elect_one_pred() {
    uint32_t pred;
    asm volatile(
        "{\n\t"
        ".reg .pred p;\n\t"
        "elect.sync _|p, 0xFFFFFFFF;\n\t"
        "selp.b32 %0, 1, 0, p;\n\t"
        "}"
        : "=r"(pred));
    return pred;
}

__device__ __forceinline__ uint32_t smem_to_u32(const void* smem_ptr) {
    uint32_t addr;
    asm("{ .reg .u64 tmp; cvta.to.shared.u64 tmp, %1; cvt.u32.u64 %0, tmp; }"
        : "=r"(addr) : "l"(smem_ptr));
    return addr;
}

// Single-instruction MUFU tanh (sm_75+). Max abs err ~1e-5 — far inside the
// 1e-3 rel-err budget. sigmoid(x) == 0.5*tanh(0.5x)+0.5 exactly.
__device__ __forceinline__ float fast_tanh(float x) {
    float y;
    asm("tanh.approx.f32 %0, %1;" : "=f"(y) : "f"(x));
    return y;
}

// SW64 swizzle: atom = 8 rows x 64 bytes
#define SMEM_SWIZZLE_64B(byte_offset) \
    ((byte_offset) ^ (((byte_offset) >> 3) & 0x30))

// SW64 smem descriptor: layout=4, version=1 (Blackwell), SBO=32 (512B per
// 8-row group), LBO=1 (16B inner stride). Rows are 64B wide.
static constexpr uint64_t SMEM_DESC_BASE_SW64 =
    (uint64_t(4)  << 61)
    | (uint64_t(1) << 46)
    | (uint64_t(32) << 32)
    | (uint64_t(1) << 16);

#define MAKE_SMEM_DESC64(base_addr) \
    (SMEM_DESC_BASE_SW64 | ((uint64_t)((base_addr) >> 4) & 0x3FFF))

#define TCGEN05_ALLOC(smem_result_addr, nCols) \
    asm volatile( \
        "tcgen05.alloc.cta_group::1.sync.aligned.shared::cta.b32 [%0], %1;" \
        :: "r"((uint32_t)(smem_result_addr)), "r"((uint32_t)(nCols)) \
        : "memory")

#define TCGEN05_DEALLOC(tmem_addr, nCols) \
    asm volatile( \
        "tcgen05.dealloc.cta_group::1.sync.aligned.b32 %0, %1;" \
        :: "r"(tmem_addr), "r"((uint32_t)(nCols)))

#define TCGEN05_RELINQUISH_ALLOC_PERMIT() \
    asm volatile("tcgen05.relinquish_alloc_permit.cta_group::1.sync.aligned;")

#define TCGEN05_COMMIT(mbar_smem_addr) \
    asm volatile( \
        "tcgen05.commit.cta_group::1.mbarrier::arrive::one.shared::cluster.b64 [%0];" \
        :: "r"((uint32_t)(mbar_smem_addr)) \
        : "memory")

#define TCGEN05_FENCE_AFTER() \
    asm volatile("tcgen05.fence::after_thread_sync;" ::: "memory")

#define TCGEN05_FENCE_BEFORE() \
    asm volatile("tcgen05.fence::before_thread_sync;" ::: "memory")

#define TCGEN05_WAIT_LD() \
    asm volatile("tcgen05.wait::ld.sync.aligned;" ::: "memory")

#define FENCE_PROXY_ASYNC_SHARED_CTA() \
    asm volatile("fence.proxy.async.shared::cta;" ::: "memory")

#define MBARRIER_INIT(mbar_smem_addr, count) \
    asm volatile( \
        "mbarrier.init.shared.b64 [%0], %1;" \
        :: "r"((uint32_t)(mbar_smem_addr)), "r"((uint32_t)(count)) \
        : "memory")

#define MBARRIER_ARRIVE(mbar_smem_addr) \
    asm volatile( \
        "mbarrier.arrive.release.cta.shared::cta.b64 _, [%0];" \
        :: "r"((uint32_t)(mbar_smem_addr)) \
        : "memory")

#define MBARRIER_WAIT_PARITY(mbar_smem_addr, phase_parity) do { \
    uint32_t _mbar = (uint32_t)(mbar_smem_addr); \
    uint32_t _parity = (uint32_t)(phase_parity); \
    uint32_t _done; \
    asm volatile( \
        "{\n\t" \
        ".reg .pred p;\n\t" \
        "mbarrier.try_wait.parity.acquire.cta.shared::cta.b64 p, [%1], %2;\n\t" \
        "selp.b32 %0, 1, 0, p;\n\t" \
        "}" \
        : "=r"(_done) : "r"(_mbar), "r"(_parity) : "memory"); \
    if (!_done) { \
        asm volatile( \
            "{\n\t" \
            ".reg .pred P1;\n\t" \
            "WAIT_LOOP_%=:\n\t" \
            "mbarrier.try_wait.parity.acquire.cta.shared::cta.b64 P1, [%0], %1, 0x989680;\n\t" \
            "@P1 bra.uni WAIT_DONE_%=;\n\t" \
            "bra.uni WAIT_LOOP_%=;\n\t" \
            "WAIT_DONE_%=:\n\t" \
            "}" \
            :: "r"(_mbar), "r"(_parity) : "memory"); \
    } \
} while(0)

#define TCGEN05_LD_32X32B_X16(r, tmem_addr) \
    asm volatile( \
        "tcgen05.ld.sync.aligned.32x32b.x16.b32 " \
        "{%0, %1, %2, %3, %4, %5, %6, %7, " \
        " %8, %9, %10, %11, %12, %13, %14, %15}, [%16];" \
        : "=r"((r)[0]),  "=r"((r)[1]),  "=r"((r)[2]),  "=r"((r)[3]), \
          "=r"((r)[4]),  "=r"((r)[5]),  "=r"((r)[6]),  "=r"((r)[7]), \
          "=r"((r)[8]),  "=r"((r)[9]),  "=r"((r)[10]), "=r"((r)[11]), \
          "=r"((r)[12]), "=r"((r)[13]), "=r"((r)[14]), "=r"((r)[15]) \
        : "r"(tmem_addr))

#if HAS_TC
// SS-mode cg1 bf16 MMA (kind::f16), fp32 accumulate in TMEM.
__device__ __forceinline__ void mma_f16_ss(uint32_t d_tmem, uint64_t a_desc,
                                           uint64_t b_desc, uint32_t idesc,
                                           uint32_t en) {
    asm volatile(
        "{\n\t"
        ".reg .pred p;\n\t"
        "setp.ne.u32 p, %5, 0;\n\t"
        "tcgen05.mma.cta_group::1.kind::f16 [%0], %1, %2, %3, {%4, %4, %4, %4}, p;\n\t"
        "}"
        :: "r"(d_tmem), "l"(a_desc), "l"(b_desc), "r"(idesc), "r"(0u), "r"(en)
        : "memory");
}

// 16-byte async copy, L2-only (.cg): streamed weights have no L1 reuse.
__device__ __forceinline__ void cp_async_16(uint32_t saddr, const void* gptr) {
    asm volatile(
        "{\n\t"
        ".reg .u64 g;\n\t"
        "cvta.to.global.u64 g, %1;\n\t"
        "cp.async.cg.shared.global [%0], [g], 16;\n\t"
        "}"
        :: "r"(saddr), "l"(gptr) : "memory");
}
#endif

// ============================================================================
// Shared memory layout. K-chunk = 32 (64B rows, SW64). Two pipeline stages.
// H-SPLIT: each CTA handles 64 of the 128 H columns -> B tile = 192 gate rows.
// Per stage: A_HI 8KB | A_LO 8KB | B_HI 12KB | B_LO 12KB = 40KB.
// Total 84KB per CTA -> 2 CTAs per SM (smem, TMEM 2x256 cols, regs).
// ============================================================================
static constexpr int SMEM_TMEMPTR   = 0;
static constexpr int SMEM_DONE0     = 8;     // stage 0 "mma done" (commit)
static constexpr int SMEM_DONE1     = 16;    // stage 1 "mma done"
static constexpr int SMEM_FULL0     = 24;    // stage 0 "tiles ready" (256 arrivals)
static constexpr int SMEM_FULL1     = 32;    // stage 1 "tiles ready"
static constexpr int SMEM_BIAS      = 64;    // 256 floats (r|z|xn_b|hn_b), 64 each
static constexpr int SMEM_STAGES    = 2048;
static constexpr int SMEM_STAGE_SZ  = 40960;
static constexpr int OFF_A_HI       = 0;      // 128 x 64B = 8 KB
static constexpr int OFF_A_LO       = 8192;   // 8 KB
static constexpr int OFF_B_HI       = 16384;  // 192 x 64B = 12 KB
static constexpr int OFF_B_LO       = 28672;  // 12 KB
static constexpr int SMEM_TOTAL     = SMEM_STAGES + 2 * SMEM_STAGE_SZ; // 83968

// idesc kind::f16 cg1: dtype=F32, atype=btype=BF16, N=64, M=128
static constexpr uint32_t IDESC =
    (1u << 4) | (1u << 7) | (1u << 10) | ((64u / 8) << 17) | ((128u / 16) << 24);

// ============================================================================
// Prep kernel: split fp32 weights into bf16 hi/lo pairs
// ============================================================================
__global__ void __launch_bounds__(256) gru_prep(const float* __restrict__ w_ih,
                                                const float* __restrict__ w_hh) {
    int i = blockIdx.x * 256 + threadIdx.x;
    if (i >= W_ELEMS) return;
    float v = w_ih[i];
    __nv_bfloat16 h = __float2bfloat16(v);
    g_wih_hi[i] = h;
    g_wih_lo[i] = __float2bfloat16(v - __bfloat162float(h));
    v = w_hh[i];
    h = __float2bfloat16(v);
    g_whh_hi[i] = h;
    g_whh_lo[i] = __float2bfloat16(v - __bfloat162float(h));
}

// ============================================================================
// Main fused GRU kernel. One CTA = (u, 128-row batch tile, 64-col H half).
// Pairs (hh=0 / hh=1) are adjacent in blockIdx.x so the duplicated A reads
// L2-hit. 256 threads, 2 CTAs/SM.
// TMEM D (256 cols): [0:64)=r_sum [64:128)=z_sum [128:192)=xn [192:256)=hn
// Pipeline: 8 chunks (2 sides x 4 K32-chunks), 2 smem stages. A-tile LDGs are
// register-prefetched ONE CHUNK AHEAD (issued before the backpressure wait),
// hiding the DRAM latency that bound R15.
// ============================================================================
__global__ void __launch_bounds__(256, 2) gru_main(
    const float* __restrict__ inputs,
    const float* __restrict__ hidden,
    const float* __restrict__ w_ih,
    const float* __restrict__ w_hh,
    const float* __restrict__ b_ih,
    const float* __restrict__ b_hh,
    float* __restrict__ out)
{
    extern __shared__ __align__(1024) char smem[];
    const int tid = threadIdx.x;
    const int u   = blockIdx.y;
    const int hh  = blockIdx.x & 1;          // H half: cols [hh*64, hh*64+64)
    const int b0  = (blockIdx.x >> 1) * 128; // batch-row tile

#if HAS_TC
    const uint32_t smem_base = smem_to_u32(smem);
    const int wid = tid >> 5;
    const int lid = tid & 31;

    if (wid == 0) {
        TCGEN05_ALLOC(smem_base + SMEM_TMEMPTR, 256);
        TCGEN05_RELINQUISH_ALLOC_PERMIT();
    }
    if (tid == 0) {
        MBARRIER_INIT(smem_base + SMEM_DONE0, 1);
        MBARRIER_INIT(smem_base + SMEM_DONE1, 1);
        MBARRIER_INIT(smem_base + SMEM_FULL0, 256);
        MBARRIER_INIT(smem_base + SMEM_FULL1, 256);
    }

    // bias: 4 x 64 floats for this H half: [r_sum | z_sum | xn_b | hn_b]
    float* bias = (float*)(smem + SMEM_BIAS);
    if (tid < 64) {
        const int c = tid;
        const int gr = 0 * H_DIM + hh * 64 + c;   // r row
        const int gz = 1 * H_DIM + hh * 64 + c;   // z row
        const int gn = 2 * H_DIM + hh * 64 + c;   // n row
        bias[c]       = b_ih[u * G3 + gr] + b_hh[u * G3 + gr];
        bias[64 + c]  = b_ih[u * G3 + gz] + b_hh[u * G3 + gz];
        bias[128 + c] = b_ih[u * G3 + gn];
        bias[192 + c] = b_hh[u * G3 + gn];
    }
    __syncthreads();   // mbarrier init + bias visible to all threads

    uint32_t tmem_base;
    asm volatile("ld.shared.b32 %0, [%1];"
                 : "=r"(tmem_base) : "r"(smem_base + SMEM_TMEMPTR));

    // Per-thread A-tile addressing: 4 fixed rows, chunk selects side + k0.
    // a_base[i] = &side[(b0+row)*U + u][0] for this thread's i-th row.
    const float* a_base_in[4];
    const float* a_base_hi[4];
    uint32_t     a_soff[4];     // swizzled smem offset for this thread's slot
    #pragma unroll
    for (int i = 0; i < 4; i++) {
        const int q    = tid + i * 256;
        const int row  = q >> 3;
        const int colf = (q & 7) << 2;
        const size_t go = (((size_t)(b0 + row)) * U_DIM + u) * I_DIM + colf;
        a_base_in[i] = inputs + go;
        a_base_hi[i] = hidden + go;
        a_soff[i]    = SMEM_SWIZZLE_64B((uint32_t)(row * 64 + colf * 2));
    }

    // Register prefetch buffer: chunk 0 (x-side, k0=0)
    float4 a_buf[4];
    #pragma unroll
    for (int i = 0; i < 4; i++)
        a_buf[i] = *(const float4*)(a_base_in[i]);

    // ---------------- pipelined mainloop: 8 chunks, 2 stages -----------------
    for (int ch = 0; ch < 8; ch++) {
        const int ph = ch >> 2;          // 0: x-side, 1: h-side
        const int cc = ch & 3;           // K32 chunk within side
        const int k0 = cc * 32;
        const int s  = ch & 1;
        const int stage = SMEM_STAGES + s * SMEM_STAGE_SZ;
        const uint32_t done_mbar = smem_base + (s ? SMEM_DONE1 : SMEM_DONE0);
        const uint32_t full_mbar = smem_base + (s ? SMEM_FULL1 : SMEM_FULL0);

        const __nv_bfloat16* wh = ph ? g_whh_hi : g_wih_hi;
        const __nv_bfloat16* wl = ph ? g_whh_lo : g_wih_lo;

        // Prefetch NEXT chunk's A tile into registers (crosses the done-wait:
        // pure LDG -> regs, no smem hazard). ~1 chunk of DRAM-latency cover.
        float4 a_nxt[4];
        if (ch < 7) {
            const int nph = (ch + 1) >> 2;
            const int nk0 = ((ch + 1) & 3) * 32;
            #pragma unroll
            for (int i = 0; i < 4; i++)
                a_nxt[i] = *(const float4*)((nph ? a_base_hi[i] : a_base_in[i]) + nk0);
        }

        // Backpressure: stage reused at ch-2; wait for its MMA commit.
        if (ch >= 2) MBARRIER_WAIT_PARITY(done_mbar, ((ch >> 1) + 1) & 1);

        // B tile via cp.async: 3 gates x 64 rows (this H half) x 64B, hi+lo
        #pragma unroll
        for (int i = 0; i < 3; i++) {
            const int q  = tid + i * 256;          // [0,768)
            const int lr = q >> 2;                 // local row 0..191
            const int gate = lr >> 6;              // 0=r 1=z 2=n
            const int g  = gate * H_DIM + hh * 64 + (lr & 63);
            const int ce = (q & 3) << 3;           // element col (x8 bf16)
            const size_t gi = (((size_t)u * G3) + g) * I_DIM + k0 + ce;
            const uint32_t off = SMEM_SWIZZLE_64B((uint32_t)(lr * 64 + (q & 3) * 16));
            cp_async_16(smem_base + stage + OFF_B_HI + off, wh + gi);
            cp_async_16(smem_base + stage + OFF_B_LO + off, wl + gi);
        }
        asm volatile("cp.async.commit_group;" ::: "memory");

        // A tile: convert prefetched registers -> bf16 hi/lo, SW64 smem
        #pragma unroll
        for (int i = 0; i < 4; i++) {
            const float4 v = a_buf[i];
            __nv_bfloat162 h0 = __float22bfloat162_rn(make_float2(v.x, v.y));
            __nv_bfloat162 h1 = __float22bfloat162_rn(make_float2(v.z, v.w));
            float2 r0 = make_float2(v.x - __bfloat162float(h0.x),
                                    v.y - __bfloat162float(h0.y));
            float2 r1 = make_float2(v.z - __bfloat162float(h1.x),
                                    v.w - __bfloat162float(h1.y));
            __nv_bfloat162 l0 = __float22bfloat162_rn(r0);
            __nv_bfloat162 l1 = __float22bfloat162_rn(r1);
            *(uint2*)(smem + stage + OFF_A_HI + a_soff[i]) =
                make_uint2(*(uint32_t*)&h0, *(uint32_t*)&h1);
            *(uint2*)(smem + stage + OFF_A_LO + a_soff[i]) =
                make_uint2(*(uint32_t*)&l0, *(uint32_t*)&l1);
        }

        asm volatile("cp.async.wait_group 0;" ::: "memory");
        FENCE_PROXY_ASYNC_SHARED_CTA();
        MBARRIER_ARRIVE(full_mbar);

        // Rotate prefetch buffer.
        #pragma unroll
        for (int i = 0; i < 4; i++) a_buf[i] = a_nxt[i];

        // Single MMA agent: wait all 256 producer arrivals, then issue.
        // 3 split terms x 2 K16 steps x 3 gate tiles (N=64) = 18 dispatches.
        if (wid == 0) {
            if (elect_one_pred()) {
                MBARRIER_WAIT_PARITY(full_mbar, (ch >> 1) & 1);
                const uint32_t sb = smem_base + stage;
                const uint64_t adh = MAKE_SMEM_DESC64(sb + OFF_A_HI);
                const uint64_t adl = MAKE_SMEM_DESC64(sb + OFF_A_LO);
                const uint64_t bdh = MAKE_SMEM_DESC64(sb + OFF_B_HI);
                const uint64_t bdl = MAKE_SMEM_DESC64(sb + OFF_B_LO);
                #pragma unroll
                for (int term = 0; term < 3; term++) {
                    const uint64_t ad = (term == 2) ? adl : adh;
                    const uint64_t bd = (term == 1) ? bdl : bdh;
                    #pragma unroll
                    for (int ks = 0; ks < 2; ks++) {
                        #pragma unroll
                        for (int nt = 0; nt < 3; nt++) {
                            // gate tiles: nt 0=r, 1=z, 2=n (xn on ph0, hn on ph1)
                            const uint32_t dcol =
                                (ph == 1 && nt == 2) ? 192u : (uint32_t)(nt * 64);
                            const uint32_t first =
                                (cc == 0 && term == 0 && ks == 0) ? 1u : 0u;
                            uint32_t en;
                            if (ph == 0)
                                en = first ? 0u : 1u;           // r,z,xn first touch
                            else
                                en = (nt < 2) ? 1u : (first ? 0u : 1u); // hn first
                            mma_f16_ss(tmem_base + dcol,
                                       ad + ks * 2,
                                       bd + nt * 256 + ks * 2,
                                       IDESC, en);
                        }
                    }
                }
                TCGEN05_COMMIT(done_mbar);
            }
        }
    }

    // ---------------- epilogue: TMEM -> GRU elementwise -> GMEM --------------
    // Warps 0-3 local cols [0,32), warps 4-7 [32,64); TMEM subpart = wid & 3.
    const int row = (wid & 3) * 32 + lid;
    const int c0  = (wid >> 2) * 32;
    const float* hrow = hidden + (((size_t)(b0 + row)) * U_DIM + u) * H_DIM + hh * 64;
    float*       orow = out    + (((size_t)(b0 + row)) * U_DIM + u) * H_DIM + hh * 64;

    // Prefetch epilogue hidden (first block) BEFORE the final done-waits.
    float4 hv0[4];
    {
        const float4* hp = (const float4*)(hrow + c0);
        hv0[0] = hp[0]; hv0[1] = hp[1]; hv0[2] = hp[2]; hv0[3] = hp[3];
    }

    // Final commits: each stage committed 4 times -> parity 1.
    MBARRIER_WAIT_PARITY(smem_base + SMEM_DONE0, 1);
    MBARRIER_WAIT_PARITY(smem_base + SMEM_DONE1, 1);
    TCGEN05_FENCE_AFTER();

    for (int half = 0; half < 2; half++) {
        const int cb = c0 + half * 16;
        uint32_t rr[16], zz[16], xn[16], hn[16];
        TCGEN05_LD_32X32B_X16(rr, tmem_base + cb);
        TCGEN05_LD_32X32B_X16(zz, tmem_base + 64 + cb);
        TCGEN05_LD_32X32B_X16(xn, tmem_base + 128 + cb);
        TCGEN05_LD_32X32B_X16(hn, tmem_base + 192 + cb);
        TCGEN05_WAIT_LD();

        float4 hv[4];
        if (half == 0) {
            hv[0] = hv0[0]; hv[1] = hv0[1]; hv[2] = hv0[2]; hv[3] = hv0[3];
        } else {
            const float4* hp = (const float4*)(hrow + cb);
            hv[0] = hp[0]; hv[1] = hp[1]; hv[2] = hp[2]; hv[3] = hp[3];
        }
        const float* hvf = (const float*)hv;

        float res[16];
        #pragma unroll
        for (int j = 0; j < 16; j++) {
            const int c = cb + j;                 // local col in [0,64)
            const float vr = __uint_as_float(rr[j]) + bias[c];
            const float vz = __uint_as_float(zz[j]) + bias[64 + c];
            // sigmoid(x) = 0.5*tanh(0.5x)+0.5 (exact identity, MUFU.TANH)
            const float r  = fmaf(fast_tanh(0.5f * vr), 0.5f, 0.5f);
            const float z  = fmaf(fast_tanh(0.5f * vz), 0.5f, 0.5f);
            const float vn = __uint_as_float(xn[j]) + bias[128 + c]
                           + r * (__uint_as_float(hn[j]) + bias[192 + c]);
            const float n  = fast_tanh(vn);
            res[j] = n + z * (hvf[j] - n);        // (1-z)*n + z*h
        }
        TCGEN05_FENCE_BEFORE();
        float4* op = (float4*)(orow + cb);
        op[0] = ((float4*)res)[0];
        op[1] = ((float4*)res)[1];
        op[2] = ((float4*)res)[2];
        op[3] = ((float4*)res)[3];
    }

    __syncthreads();
    if (wid == 0) {
        TCGEN05_DEALLOC(tmem_base, 256);
    }

#else  // ---------------- fallback: plain fp32 FFMA (non-sm_103a targets) ----
    // Correct but slow; only executes if the runtime ever JITs the plain
    // compute_103 PTX instead of using the sm_103a cubin.
    float* xs = (float*)smem;              // 128 x 128
    float* hs = xs + 128 * 128;            // 128 x 128
    for (int q = tid; q < 128 * 128; q += 256) {
        const int row = q >> 7, col = q & 127;
        const size_t base = (((size_t)(b0 + row)) * U_DIM + u) * I_DIM + col;
        xs[q] = inputs[base];
        hs[q] = hidden[base];
    }
    __syncthreads();

    if (tid < 128) {
        const float* xr_ = xs + tid * 128;
        const float* hr_ = hs + tid * 128;
        float* orow = out + (((size_t)(b0 + tid)) * U_DIM + u) * H_DIM;

        for (int cl = 0; cl < 64; cl++) {
            const int c = hh * 64 + cl;
            float axr = b_ih[u * G3 + c],       ahr = b_hh[u * G3 + c];
            float axz = b_ih[u * G3 + 128 + c], ahz = b_hh[u * G3 + 128 + c];
            float axn = b_ih[u * G3 + 256 + c], ahn = b_hh[u * G3 + 256 + c];
            const float* wir = w_ih + (((size_t)u * G3) + c) * I_DIM;
            const float* whr = w_hh + (((size_t)u * G3) + c) * I_DIM;
            for (int k = 0; k < I_DIM; k++) {
                const float xv = xr_[k], hv = hr_[k];
                axr += xv * wir[k];
                axz += xv * wir[128 * I_DIM + k];
                axn += xv * wir[256 * I_DIM + k];
                ahr += hv * whr[k];
                ahz += hv * whr[128 * I_DIM + k];
                ahn += hv * whr[256 * I_DIM + k];
            }
            const float r = 1.f / (1.f + expf(-(axr + ahr)));
            const float z = 1.f / (1.f + expf(-(axz + ahz)));
            const float n = tanhf(axn + r * ahn);
            orow[c] = (1.f - z) * n + z * hr_[c];
        }
    }
#endif
}

// ============================================================================
// kernel_launch — graph-capturable, allocation-free
// ============================================================================
extern "C" void kernel_launch(void* const* d_in, const int* in_sizes, int n_in,
                              void* d_out, int out_size) {
    const float* inputs = (const float*)d_in[0];
    const float* hidden = (const float*)d_in[1];
    const float* w_ih   = (const float*)d_in[2];
    const float* w_hh   = (const float*)d_in[3];
    const float* b_ih   = (const float*)d_in[4];
    const float* b_hh   = (const float*)d_in[5];
    float* out = (float*)d_out;

    const int B = in_sizes[0] / (U_DIM * I_DIM);   // 8192

    gru_prep<<<(W_ELEMS + 255) / 256, 256>>>(w_ih, w_hh);

    cudaFuncSetAttribute(gru_main,
                         cudaFuncAttributeMaxDynamicSharedMemorySize, SMEM_TOTAL);
    // blockIdx.x = (batch-tile << 1) | H-half  -> pairs adjacent for L2 reuse
    gru_main<<<dim3((B / 128) * 2, U_DIM), 256, SMEM_TOTAL>>>(
        inputs, hidden, w_ih, w_hh, b_ih, b_hh, out);
}